// round 13
// baseline (speedup 1.0000x reference)
#include <cuda_runtime.h>
#include <cuda_fp16.h>
#include <cstdint>

#define N_NODES 50000
#define N_EDGES 800000
#define IN_DIM  512
#define HID     96
#define OUTD    64
#define SCAN_BS 512
#define NBLK    ((N_NODES + SCAN_BS - 1) / SCAN_BS)   // 98

// x-conversion / GEMM0 pipeline chunking
#define N_CHUNK   4
#define CH_ROWS   12544                   // 98 blocks * 128 rows
#define NX4       (N_NODES * IN_DIM / 4)  // 6,400,000 float4
#define CH4       (CH_ROWS * IN_DIM / 4)  // float4 per chunk

// fp16 weight pool offsets (halves)
#define W16_W0  0
#define W16_W1  (IN_DIM * HID)
#define W16_W2  (W16_W1 + HID * HID)
#define W16_FC  (W16_W2 + HID * HID)
#define W16_TOT (W16_FC + HID * OUTD)

// Scratch (alloc-free rule: __device__ globals)
__device__ __align__(16) __half g_x16[N_NODES * IN_DIM];
__device__ __align__(16) __half g_w16[W16_TOT];
__device__ __align__(16) __half g_h16[N_NODES * HID];   // GEMM out (gather input)
__device__ __align__(16) __half g_a16[N_NODES * HID];   // relu(agg) (next GEMM's A)
__device__ float  g_dinv[N_NODES];
__device__ int    g_deg[N_NODES];
__device__ int    g_rowptr[N_NODES + 1];
__device__ int    g_cursor[N_NODES];
__device__ int    g_bsum[128];
__device__ __align__(16) float2 g_edge[N_EDGES];        // (.x = src bits, .y = w)

// ---------------- fp32 -> fp16 conversion ----------------
__device__ __forceinline__ void st_half4(__half* p, float4 v) {
    __half2 a = __floats2half2_rn(v.x, v.y);
    __half2 b = __floats2half2_rn(v.z, v.w);
    uint2 u;
    u.x = *reinterpret_cast<uint32_t*>(&a);
    u.y = *reinterpret_cast<uint32_t*>(&b);
    *reinterpret_cast<uint2*>(p) = u;
}

// weights only (runs first on s2; tiny)
__global__ void k_cvt_w(const float* __restrict__ W0, const float* __restrict__ W1,
                        const float* __restrict__ W2, const float* __restrict__ fcW)
{
    constexpr int S0 = IN_DIM * HID / 4;
    constexpr int S1 = HID * HID / 4;
    constexpr int S3 = HID * OUTD / 4;
    int j = blockIdx.x * blockDim.x + threadIdx.x;
    const float* src; __half* dst;
    if (j < S0)                    { src = W0 + j * 4;               dst = &g_w16[W16_W0 + j * 4]; }
    else if (j < S0 + S1)          { j -= S0;  src = W1 + j * 4;     dst = &g_w16[W16_W1 + j * 4]; }
    else if (j < S0 + 2 * S1)      { j -= S0 + S1; src = W2 + j * 4; dst = &g_w16[W16_W2 + j * 4]; }
    else if (j < S0 + 2 * S1 + S3) { j -= S0 + 2 * S1; src = fcW + j * 4; dst = &g_w16[W16_FC + j * 4]; }
    else return;
    float4 v = *reinterpret_cast<const float4*>(src);
    st_half4(dst, v);
}

// x chunk: float4 indices [start4, end4)
__global__ void k_cvt_x(const float* __restrict__ x, int start4, int end4) {
    int i = start4 + blockIdx.x * blockDim.x + threadIdx.x;
    if (i < end4) {
        float4 v = *reinterpret_cast<const float4*>(x + (size_t)i * 4);
        st_half4(&g_x16[(size_t)i * 4], v);
    }
}

// ---------------- degree / normalization ----------------
__global__ void k_count_deg(const int* __restrict__ dst) {
    int e = blockIdx.x * blockDim.x + threadIdx.x;
    if (e < N_EDGES) atomicAdd(&g_deg[dst[e]], 1);
}

__global__ void k_dinv() {
    int i = blockIdx.x * blockDim.x + threadIdx.x;
    if (i < N_NODES) g_dinv[i] = rsqrtf((float)g_deg[i] + 1.0f);
}

// ---------------- CSR build ----------------
__global__ __launch_bounds__(SCAN_BS) void k_scan1() {
    __shared__ int sh[2][SCAN_BS];
    int t = threadIdx.x;
    int i = blockIdx.x * SCAN_BS + t;
    int v = (i < N_NODES) ? g_deg[i] : 0;
    sh[0][t] = v;
    __syncthreads();
    int cur = 0;
#pragma unroll
    for (int off = 1; off < SCAN_BS; off <<= 1) {
        int x = sh[cur][t];
        if (t >= off) x += sh[cur][t - off];
        sh[cur ^ 1][t] = x;
        cur ^= 1;
        __syncthreads();
    }
    int incl = sh[cur][t];
    if (i < N_NODES) g_rowptr[i] = incl - v;
    if (t == SCAN_BS - 1) g_bsum[blockIdx.x] = incl;
}

__global__ void k_scan2() {
    __shared__ int sh[2][128];
    int t = threadIdx.x;
    int v = (t < NBLK) ? g_bsum[t] : 0;
    sh[0][t] = v;
    __syncthreads();
    int cur = 0;
#pragma unroll
    for (int off = 1; off < 128; off <<= 1) {
        int x = sh[cur][t];
        if (t >= off) x += sh[cur][t - off];
        sh[cur ^ 1][t] = x;
        cur ^= 1;
        __syncthreads();
    }
    if (t < NBLK) g_bsum[t] = sh[cur][t] - v;
}

__global__ void k_scan3() {
    int i = blockIdx.x * blockDim.x + threadIdx.x;
    if (i < N_NODES) {
        int r = g_rowptr[i] + g_bsum[i / SCAN_BS];
        g_rowptr[i] = r;
        g_cursor[i] = r;
    }
    if (i == 0) g_rowptr[N_NODES] = N_EDGES;
}

__global__ void k_fill(const int* __restrict__ src, const int* __restrict__ dst) {
    int e = blockIdx.x * blockDim.x + threadIdx.x;
    if (e >= N_EDGES) return;
    int s = src[e], d = dst[e];
    int pos = atomicAdd(&g_cursor[d], 1);
    g_edge[pos] = make_float2(__int_as_float(s), g_dinv[s] * g_dinv[d]);
}

// ---------------- MMA helpers ----------------
__device__ __forceinline__ uint32_t smem_u32(const void* p) {
    return (uint32_t)__cvta_generic_to_shared(p);
}

__device__ __forceinline__ void cp16(uint32_t dst, const void* src) {
    asm volatile("cp.async.cg.shared.global [%0], [%1], 16;" :: "r"(dst), "l"(src));
}

__device__ __forceinline__ void ldm_x4(uint32_t* d, uint32_t addr) {
    asm volatile("ldmatrix.sync.aligned.m8n8.x4.shared.b16 {%0,%1,%2,%3}, [%4];"
                 : "=r"(d[0]), "=r"(d[1]), "=r"(d[2]), "=r"(d[3]) : "r"(addr));
}

__device__ __forceinline__ void ldm_x4_t(uint32_t* d, uint32_t addr) {
    asm volatile("ldmatrix.sync.aligned.m8n8.x4.trans.shared.b16 {%0,%1,%2,%3}, [%4];"
                 : "=r"(d[0]), "=r"(d[1]), "=r"(d[2]), "=r"(d[3]) : "r"(addr));
}

__device__ __forceinline__ void mma_f16(float* c, const uint32_t* a, const uint32_t* b) {
    asm volatile(
        "mma.sync.aligned.m16n8k16.row.col.f32.f16.f16.f32 "
        "{%0,%1,%2,%3}, {%4,%5,%6,%7}, {%8,%9}, {%0,%1,%2,%3};"
        : "+f"(c[0]), "+f"(c[1]), "+f"(c[2]), "+f"(c[3])
        : "r"(a[0]), "r"(a[1]), "r"(a[2]), "r"(a[3]),
          "r"(b[0]), "r"(b[1]));
}

// ---------------- fp16 tensor-core GEMM: BK=32, 3-stage cp.async ----------------
// C[M,BN] = A[M,K] @ W[K,BN], fp16 in, fp32 acc. BM=128, 256 threads (8 warps 4x2).
// row_off: M-slice offset (pipelined GEMM0 slices); block_row = row_off + blockIdx*BM.
// LAYER_EPI: write H16 = half(C). Else: OUT = C + bias (fp32).
template<int BN, bool LAYER_EPI>
__global__ __launch_bounds__(256, 3) void k_gemm_tc(
    const __half* __restrict__ Ah, const __half* __restrict__ Wh,
    const float* __restrict__ bias, __half* __restrict__ H16,
    float* __restrict__ OUT, int M, int K, int row_off)
{
    constexpr int BM = 128, BK = 32, STAGES = 3;
    constexpr int WN = BN / 2;
    constexpr int NA = WN / 8;
    constexpr int AKP = BK + 8;
    constexpr int BNP = BN + 8;
    constexpr int A_ST = BM * AKP;
    constexpr int BCH = BK * BN / 8;

    extern __shared__ __half smem[];
    __half* As = smem;
    __half* Bs = smem + STAGES * A_ST;

    const int tid  = threadIdx.x;
    const int wid  = tid >> 5;
    const int lane = tid & 31;
    const int g    = lane >> 2;
    const int tq   = lane & 3;
    const int wm   = wid & 3;
    const int wn   = wid >> 2;
    const int block_row = row_off + blockIdx.x * BM;

    float acc[2][NA][4];
#pragma unroll
    for (int mi = 0; mi < 2; mi++)
#pragma unroll
        for (int ni = 0; ni < NA; ni++)
#pragma unroll
            for (int q = 0; q < 4; q++) acc[mi][ni][q] = 0.0f;

    const int ar0 = tid >> 2,          ar1 = (tid + 256) >> 2;
    const int ac0 = (tid & 3) * 8,     ac1 = ((tid + 256) & 3) * 8;
    int grow0 = block_row + ar0; if (grow0 >= M) grow0 = M - 1;
    int grow1 = block_row + ar1; if (grow1 >= M) grow1 = M - 1;
    const __half* aSrc0 = Ah + (size_t)grow0 * K + ac0;
    const __half* aSrc1 = Ah + (size_t)grow1 * K + ac1;

    const int br0 = tid / (BN / 8),         bc0 = (tid % (BN / 8)) * 8;
    const int br1 = (tid + 256) / (BN / 8), bc1 = ((tid + 256) % (BN / 8)) * 8;

    auto issue = [&](int t, int buf) {
        int k0 = t * BK;
        cp16(smem_u32(&As[(buf * BM + ar0) * AKP + ac0]), aSrc0 + k0);
        cp16(smem_u32(&As[(buf * BM + ar1) * AKP + ac1]), aSrc1 + k0);
        cp16(smem_u32(&Bs[(buf * BK + br0) * BNP + bc0]),
             Wh + (size_t)(k0 + br0) * BN + bc0);
        if (256 < BCH && tid + 256 < BCH)
            cp16(smem_u32(&Bs[(buf * BK + br1) * BNP + bc1]),
                 Wh + (size_t)(k0 + br1) * BN + bc1);
    };

    const int NT = K / BK;
#pragma unroll
    for (int s = 0; s < STAGES - 1; s++) {
        issue(s, s);
        asm volatile("cp.async.commit_group;" ::: "memory");
    }

    const int la_r = (lane & 7) + ((lane >> 3) & 1) * 8;
    const int la_c = ((lane >> 4) & 1) * 8;
    const int lb_k = (lane & 7) + ((lane >> 3) & 1) * 8;
    const int lb_n = ((lane >> 4) & 1) * 8;

    for (int t = 0; t < NT; t++) {
        asm volatile("cp.async.wait_group %0;" :: "n"(STAGES - 2) : "memory");
        __syncthreads();
        const int buf = t % STAGES;

#pragma unroll
        for (int ks = 0; ks < 2; ks++) {
            uint32_t afr[2][4];
#pragma unroll
            for (int mi = 0; mi < 2; mi++)
                ldm_x4(afr[mi], smem_u32(
                    &As[(buf * BM + wm * 32 + mi * 16 + la_r) * AKP + ks * 16 + la_c]));

            uint32_t bfr[NA][2];
#pragma unroll
            for (int ni2 = 0; ni2 < NA / 2; ni2++) {
                uint32_t tmp[4];
                ldm_x4_t(tmp, smem_u32(
                    &Bs[(buf * BK + ks * 16 + lb_k) * BNP + wn * WN + ni2 * 16 + lb_n]));
                bfr[2 * ni2][0]     = tmp[0];
                bfr[2 * ni2][1]     = tmp[1];
                bfr[2 * ni2 + 1][0] = tmp[2];
                bfr[2 * ni2 + 1][1] = tmp[3];
            }

#pragma unroll
            for (int mi = 0; mi < 2; mi++)
#pragma unroll
                for (int ni = 0; ni < NA; ni++)
                    mma_f16(acc[mi][ni], afr[mi], bfr[ni]);
        }

        int tn = t + STAGES - 1;
        if (tn < NT) issue(tn, tn % STAGES);
        asm volatile("cp.async.commit_group;" ::: "memory");
    }

    // Epilogue (fragment rows g, g+8; cols 2tq, 2tq+1)
#pragma unroll
    for (int mi = 0; mi < 2; mi++) {
        int rA = block_row + wm * 32 + mi * 16 + g;
        int rB = rA + 8;
        bool okA = rA < M, okB = rB < M;
#pragma unroll
        for (int ni = 0; ni < NA; ni++) {
            int col = wn * WN + ni * 8 + 2 * tq;
            if (LAYER_EPI) {
                if (okA)
                    *reinterpret_cast<__half2*>(&H16[(size_t)rA * BN + col])
                        = __floats2half2_rn(acc[mi][ni][0], acc[mi][ni][1]);
                if (okB)
                    *reinterpret_cast<__half2*>(&H16[(size_t)rB * BN + col])
                        = __floats2half2_rn(acc[mi][ni][2], acc[mi][ni][3]);
            } else {
                float bx = bias[col], by = bias[col + 1];
                if (okA)
                    *reinterpret_cast<float2*>(&OUT[(size_t)rA * BN + col])
                        = make_float2(acc[mi][ni][0] + bx, acc[mi][ni][1] + by);
                if (okB)
                    *reinterpret_cast<float2*>(&OUT[(size_t)rB * BN + col])
                        = make_float2(acc[mi][ni][2] + bx, acc[mi][ni][3] + by);
            }
        }
    }
}

// ---------------- CSR gather + self-loop + bias + relu (round-9 exact version) ----------------
// a16[n] = half(relu( sum_e h16[src[e]]*w[e] + h16[n]*dinv[n]^2 + bias ))
// One warp per node; lanes 0..23 own 4 consecutive columns. Simple loop — the
// empirically fastest form (all manual pipelining variants regressed).
__global__ __launch_bounds__(256) void k_gather(const float* __restrict__ bias) {
    int node = (blockIdx.x * 256 + threadIdx.x) >> 5;
    if (node >= N_NODES) return;
    int lane = threadIdx.x & 31;
    int beg = g_rowptr[node];
    int end = g_rowptr[node + 1];
    const bool active = lane < (HID / 4);   // 24 lanes
    const int coff = lane * 4;

    float4 acc = make_float4(0.f, 0.f, 0.f, 0.f);
#pragma unroll 4
    for (int e = beg; e < end; e++) {
        float2 ed = __ldg(&g_edge[e]);
        int s = __float_as_int(ed.x);
        float w = ed.y;
        if (active) {
            uint2 p = *reinterpret_cast<const uint2*>(&g_h16[(size_t)s * HID + coff]);
            float2 f0 = __half22float2(*reinterpret_cast<__half2*>(&p.x));
            float2 f1 = __half22float2(*reinterpret_cast<__half2*>(&p.y));
            acc.x = fmaf(f0.x, w, acc.x);
            acc.y = fmaf(f0.y, w, acc.y);
            acc.z = fmaf(f1.x, w, acc.z);
            acc.w = fmaf(f1.y, w, acc.w);
        }
    }
    if (active) {
        uint2 p = *reinterpret_cast<const uint2*>(&g_h16[(size_t)node * HID + coff]);
        float2 f0 = __half22float2(*reinterpret_cast<__half2*>(&p.x));
        float2 f1 = __half22float2(*reinterpret_cast<__half2*>(&p.y));
        float d = g_dinv[node];
        float dd = d * d;
        float4 b4 = *reinterpret_cast<const float4*>(&bias[coff]);
        float r0 = fmaxf(fmaf(f0.x, dd, acc.x) + b4.x, 0.f);
        float r1 = fmaxf(fmaf(f0.y, dd, acc.y) + b4.y, 0.f);
        float r2 = fmaxf(fmaf(f1.x, dd, acc.z) + b4.z, 0.f);
        float r3 = fmaxf(fmaf(f1.y, dd, acc.w) + b4.w, 0.f);
        st_half4(&g_a16[(size_t)node * HID + coff], make_float4(r0, r1, r2, r3));
    }
}

extern "C" void kernel_launch(void* const* d_in, const int* in_sizes, int n_in,
                              void* d_out, int out_size)
{
    const float* x    = (const float*)d_in[0];
    const int*   ei   = (const int*)d_in[1];
    const float* W0   = (const float*)d_in[2];
    const float* b0   = (const float*)d_in[3];
    const float* W1   = (const float*)d_in[4];
    const float* b1   = (const float*)d_in[5];
    const float* W2   = (const float*)d_in[6];
    const float* b2   = (const float*)d_in[7];
    const float* fcW  = (const float*)d_in[8];
    const float* fcb  = (const float*)d_in[9];
    float* out = (float*)d_out;

    const int* src = ei;
    const int* dst = ei + N_EDGES;

    __half* x16; cudaGetSymbolAddress((void**)&x16, g_x16);
    __half* w16; cudaGetSymbolAddress((void**)&w16, g_w16);
    __half* h16; cudaGetSymbolAddress((void**)&h16, g_h16);
    __half* a16; cudaGetSymbolAddress((void**)&a16, g_a16);
    int*    deg; cudaGetSymbolAddress((void**)&deg, g_deg);

    constexpr int SMEM_96 = 3 * (128 * 40 + 32 * (HID + 8)) * 2;   // 50688
    constexpr int SMEM_64 = 3 * (128 * 40 + 32 * (OUTD + 8)) * 2;  // 44544

    static cudaStream_t s2 = nullptr, s3 = nullptr;
    static cudaEvent_t evFork = nullptr, evJoin = nullptr;
    static cudaEvent_t evC[N_CHUNK] = {nullptr, nullptr, nullptr, nullptr};
    if (!s2) {
        cudaStreamCreateWithFlags(&s2, cudaStreamNonBlocking);
        cudaStreamCreateWithFlags(&s3, cudaStreamNonBlocking);
        cudaEventCreateWithFlags(&evFork, cudaEventDisableTiming);
        cudaEventCreateWithFlags(&evJoin, cudaEventDisableTiming);
        for (int i = 0; i < N_CHUNK; i++)
            cudaEventCreateWithFlags(&evC[i], cudaEventDisableTiming);
        cudaFuncSetAttribute(k_gemm_tc<HID, true>,
                             cudaFuncAttributeMaxDynamicSharedMemorySize, SMEM_96);
        cudaFuncSetAttribute(k_gemm_tc<OUTD, false>,
                             cudaFuncAttributeMaxDynamicSharedMemorySize, SMEM_64);
    }

    const int M = N_NODES;
    dim3 gemm_grid((M + 127) / 128);
    int gather_grid = (N_NODES * 32 + 255) / 256;

    // ---- fork s2: weight cvt, then x cvt in N_CHUNK row-chunks ----
    cudaEventRecord(evFork, 0);
    cudaStreamWaitEvent(s2, evFork, 0);
    k_cvt_w<<<(W16_TOT / 4 + 255) / 256, 256, 0, s2>>>(W0, W1, W2, fcW);
    for (int c = 0; c < N_CHUNK; c++) {
        int start4 = c * CH4;
        int end4   = (c == N_CHUNK - 1) ? NX4 : (c + 1) * CH4;
        int n4 = end4 - start4;
        k_cvt_x<<<(n4 + 255) / 256, 256, 0, s2>>>(x, start4, end4);
        cudaEventRecord(evC[c], s2);
    }

    // ---- GEMM0 as 4 M-slices on s3, each gated on its cvt chunk ----
    for (int c = 0; c < N_CHUNK; c++) {
        cudaStreamWaitEvent(s3, evC[c], 0);
        int row_off = c * CH_ROWS;
        int rows = (c == N_CHUNK - 1) ? (M - row_off) : CH_ROWS;
        int blocks = (rows + 127) / 128;
        k_gemm_tc<HID, true><<<blocks, 256, SMEM_96, s3>>>(
            x16, w16 + W16_W0, nullptr, h16, nullptr, M, IN_DIM, row_off);
    }
    cudaEventRecord(evJoin, s3);

    // ---- CSR build on main, overlapped with cvt + GEMM0 pipeline ----
    cudaMemsetAsync(deg, 0, N_NODES * sizeof(int), 0);
    k_count_deg<<<(N_EDGES + 255) / 256, 256>>>(dst);
    k_dinv<<<(N_NODES + 255) / 256, 256>>>();
    k_scan1<<<NBLK, SCAN_BS>>>();
    k_scan2<<<1, 128>>>();
    k_scan3<<<(N_NODES + 255) / 256, 256>>>();
    k_fill<<<(N_EDGES + 255) / 256, 256>>>(src, dst);

    // ---- join, then layer pipeline ----
    cudaStreamWaitEvent(0, evJoin, 0);
    k_gather<<<gather_grid, 256>>>(b0);   // a16 = relu(agg0)

    k_gemm_tc<HID, true><<<gemm_grid, 256, SMEM_96>>>(
        a16, w16 + W16_W1, nullptr, h16, nullptr, M, HID, 0);
    k_gather<<<gather_grid, 256>>>(b1);

    k_gemm_tc<HID, true><<<gemm_grid, 256, SMEM_96>>>(
        a16, w16 + W16_W2, nullptr, h16, nullptr, M, HID, 0);
    k_gather<<<gather_grid, 256>>>(b2);

    // FC head: out = a16 @ fcW + fcb
    k_gemm_tc<OUTD, false><<<gemm_grid, 256, SMEM_64>>>(
        a16, w16 + W16_FC, fcb, nullptr, out, M, HID, 0);
}

// round 14
// speedup vs baseline: 1.2571x; 1.2571x over previous
#include <cuda_runtime.h>
#include <cuda_fp16.h>
#include <cstdint>

#define N_NODES 50000
#define N_EDGES 800000
#define IN_DIM  512
#define HID     96
#define OUTD    64
#define SCAN_BS 512
#define NBLK    ((N_NODES + SCAN_BS - 1) / SCAN_BS)   // 98

// fp16 weight pool offsets (halves)
#define W16_W0  0
#define W16_W1  (IN_DIM * HID)
#define W16_W2  (W16_W1 + HID * HID)
#define W16_FC  (W16_W2 + HID * HID)
#define W16_TOT (W16_FC + HID * OUTD)

// Scratch (alloc-free rule: __device__ globals)
__device__ __align__(16) __half g_w16[W16_TOT];
__device__ __align__(16) __half g_h16[N_NODES * HID];   // GEMM out (gather input)
__device__ __align__(16) __half g_a16[N_NODES * HID];   // relu(agg) (next GEMM's A)
__device__ float  g_dinv[N_NODES];
__device__ int    g_deg[N_NODES];
__device__ int    g_rowptr[N_NODES + 1];
__device__ int    g_cursor[N_NODES];
__device__ int    g_bsum[128];
__device__ __align__(16) float2 g_edge[N_EDGES];        // (.x = src bits, .y = w)

// ---------------- fp32 -> fp16 helpers ----------------
__device__ __forceinline__ void st_half4(__half* p, float4 v) {
    __half2 a = __floats2half2_rn(v.x, v.y);
    __half2 b = __floats2half2_rn(v.z, v.w);
    uint2 u;
    u.x = *reinterpret_cast<uint32_t*>(&a);
    u.y = *reinterpret_cast<uint32_t*>(&b);
    *reinterpret_cast<uint2*>(p) = u;
}

// weights only (tiny; runs first on s2)
__global__ void k_cvt_w(const float* __restrict__ W0, const float* __restrict__ W1,
                        const float* __restrict__ W2, const float* __restrict__ fcW)
{
    constexpr int S0 = IN_DIM * HID / 4;
    constexpr int S1 = HID * HID / 4;
    constexpr int S3 = HID * OUTD / 4;
    int j = blockIdx.x * blockDim.x + threadIdx.x;
    const float* src; __half* dst;
    if (j < S0)                    { src = W0 + j * 4;               dst = &g_w16[W16_W0 + j * 4]; }
    else if (j < S0 + S1)          { j -= S0;  src = W1 + j * 4;     dst = &g_w16[W16_W1 + j * 4]; }
    else if (j < S0 + 2 * S1)      { j -= S0 + S1; src = W2 + j * 4; dst = &g_w16[W16_W2 + j * 4]; }
    else if (j < S0 + 2 * S1 + S3) { j -= S0 + 2 * S1; src = fcW + j * 4; dst = &g_w16[W16_FC + j * 4]; }
    else return;
    float4 v = *reinterpret_cast<const float4*>(src);
    st_half4(dst, v);
}

// ---------------- degree ----------------
__global__ void k_count_deg(const int* __restrict__ dst) {
    int e = blockIdx.x * blockDim.x + threadIdx.x;
    if (e < N_EDGES) atomicAdd(&g_deg[dst[e]], 1);
}

// ---------------- CSR build (scan1 also computes dinv) ----------------
__global__ __launch_bounds__(SCAN_BS) void k_scan1() {
    __shared__ int sh[2][SCAN_BS];
    int t = threadIdx.x;
    int i = blockIdx.x * SCAN_BS + t;
    int v = (i < N_NODES) ? g_deg[i] : 0;
    if (i < N_NODES) g_dinv[i] = rsqrtf((float)v + 1.0f);
    sh[0][t] = v;
    __syncthreads();
    int cur = 0;
#pragma unroll
    for (int off = 1; off < SCAN_BS; off <<= 1) {
        int x = sh[cur][t];
        if (t >= off) x += sh[cur][t - off];
        sh[cur ^ 1][t] = x;
        cur ^= 1;
        __syncthreads();
    }
    int incl = sh[cur][t];
    if (i < N_NODES) g_rowptr[i] = incl - v;
    if (t == SCAN_BS - 1) g_bsum[blockIdx.x] = incl;
}

__global__ void k_scan2() {
    __shared__ int sh[2][128];
    int t = threadIdx.x;
    int v = (t < NBLK) ? g_bsum[t] : 0;
    sh[0][t] = v;
    __syncthreads();
    int cur = 0;
#pragma unroll
    for (int off = 1; off < 128; off <<= 1) {
        int x = sh[cur][t];
        if (t >= off) x += sh[cur][t - off];
        sh[cur ^ 1][t] = x;
        cur ^= 1;
        __syncthreads();
    }
    if (t < NBLK) g_bsum[t] = sh[cur][t] - v;
}

__global__ void k_scan3() {
    int i = blockIdx.x * blockDim.x + threadIdx.x;
    if (i < N_NODES) {
        int r = g_rowptr[i] + g_bsum[i / SCAN_BS];
        g_rowptr[i] = r;
        g_cursor[i] = r;
    }
    if (i == 0) g_rowptr[N_NODES] = N_EDGES;
}

__global__ void k_fill(const int* __restrict__ src, const int* __restrict__ dst) {
    int e = blockIdx.x * blockDim.x + threadIdx.x;
    if (e >= N_EDGES) return;
    int s = src[e], d = dst[e];
    int pos = atomicAdd(&g_cursor[d], 1);
    g_edge[pos] = make_float2(__int_as_float(s), g_dinv[s] * g_dinv[d]);
}

// ---------------- MMA helpers ----------------
__device__ __forceinline__ uint32_t smem_u32(const void* p) {
    return (uint32_t)__cvta_generic_to_shared(p);
}

__device__ __forceinline__ void cp16(uint32_t dst, const void* src) {
    asm volatile("cp.async.cg.shared.global [%0], [%1], 16;" :: "r"(dst), "l"(src));
}

__device__ __forceinline__ void ldm_x4(uint32_t* d, uint32_t addr) {
    asm volatile("ldmatrix.sync.aligned.m8n8.x4.shared.b16 {%0,%1,%2,%3}, [%4];"
                 : "=r"(d[0]), "=r"(d[1]), "=r"(d[2]), "=r"(d[3]) : "r"(addr));
}

__device__ __forceinline__ void ldm_x4_t(uint32_t* d, uint32_t addr) {
    asm volatile("ldmatrix.sync.aligned.m8n8.x4.trans.shared.b16 {%0,%1,%2,%3}, [%4];"
                 : "=r"(d[0]), "=r"(d[1]), "=r"(d[2]), "=r"(d[3]) : "r"(addr));
}

__device__ __forceinline__ void mma_f16(float* c, const uint32_t* a, const uint32_t* b) {
    asm volatile(
        "mma.sync.aligned.m16n8k16.row.col.f32.f16.f16.f32 "
        "{%0,%1,%2,%3}, {%4,%5,%6,%7}, {%8,%9}, {%0,%1,%2,%3};"
        : "+f"(c[0]), "+f"(c[1]), "+f"(c[2]), "+f"(c[3])
        : "r"(a[0]), "r"(a[1]), "r"(a[2]), "r"(a[3]),
          "r"(b[0]), "r"(b[1]));
}

__device__ __forceinline__ uint32_t pack_h2(float lo, float hi) {
    __half2 h = __floats2half2_rn(lo, hi);
    return *reinterpret_cast<uint32_t*>(&h);
}

// ---------------- GEMM0 (fp32 A direct): h16 = half(x @ W0) ----------------
// A fp32 staged via cp.async; fragments built by direct smem float2 loads +
// fp16 conversion in the m16n8k16 A layout (no separate x-conversion kernel).
// BM=128, BK=32, 3 stages, 256 threads (8 warps 4x2), BN=96.
__global__ __launch_bounds__(256, 3) void k_gemm0_f32(
    const float* __restrict__ A, const __half* __restrict__ Wh,
    __half* __restrict__ H16, int M)
{
    constexpr int BN = HID, K = IN_DIM;
    constexpr int BM = 128, BK = 32, STAGES = 3;
    constexpr int WN = BN / 2;        // 48
    constexpr int NA = WN / 8;        // 6
    constexpr int AKP = BK + 4;       // 36 floats (144B rows, 16B aligned)
    constexpr int BNP = BN + 8;       // 104 halves
    constexpr int A_ST = BM * AKP;    // floats per A stage
    constexpr int BCH = BK * BN / 8;  // 384 B-chunks per tile

    extern __shared__ float smemf[];
    float*  As = smemf;                                          // [STAGES][BM][AKP] fp32
    __half* Bs = reinterpret_cast<__half*>(smemf + STAGES * A_ST); // [STAGES][BK][BNP]

    const int tid  = threadIdx.x;
    const int wid  = tid >> 5;
    const int lane = tid & 31;
    const int g    = lane >> 2;
    const int tq   = lane & 3;
    const int wm   = wid & 3;
    const int wn   = wid >> 2;
    const int block_row = blockIdx.x * BM;

    float acc[2][NA][4];
#pragma unroll
    for (int mi = 0; mi < 2; mi++)
#pragma unroll
        for (int ni = 0; ni < NA; ni++)
#pragma unroll
            for (int q = 0; q < 4; q++) acc[mi][ni][q] = 0.0f;

    // A: 128 rows x 8 chunks (16B = 4 floats) = 1024 chunks -> 4 per thread
    int arow[4], acol[4];
    const float* asrc[4];
#pragma unroll
    for (int i = 0; i < 4; i++) {
        int j = tid + i * 256;
        arow[i] = j >> 3;
        acol[i] = (j & 7) * 4;
        int grow = block_row + arow[i]; if (grow >= M) grow = M - 1;  // row-clamp safe
        asrc[i] = A + (size_t)grow * K + acol[i];
    }

    const int br0 = tid / (BN / 8),         bc0 = (tid % (BN / 8)) * 8;
    const int br1 = (tid + 256) / (BN / 8), bc1 = ((tid + 256) % (BN / 8)) * 8;

    auto issue = [&](int t, int buf) {
        int k0 = t * BK;
#pragma unroll
        for (int i = 0; i < 4; i++)
            cp16(smem_u32(&As[(buf * BM + arow[i]) * AKP + acol[i]]), asrc[i] + k0);
        cp16(smem_u32(&Bs[(buf * BK + br0) * BNP + bc0]),
             Wh + (size_t)(k0 + br0) * BN + bc0);
        if (tid + 256 < BCH)
            cp16(smem_u32(&Bs[(buf * BK + br1) * BNP + bc1]),
                 Wh + (size_t)(k0 + br1) * BN + bc1);
    };

    const int NT = K / BK;   // 16
#pragma unroll
    for (int s = 0; s < STAGES - 1; s++) {
        issue(s, s);
        asm volatile("cp.async.commit_group;" ::: "memory");
    }

    const int lb_k = (lane & 7) + ((lane >> 3) & 1) * 8;
    const int lb_n = ((lane >> 4) & 1) * 8;

    for (int t = 0; t < NT; t++) {
        asm volatile("cp.async.wait_group %0;" :: "n"(STAGES - 2) : "memory");
        __syncthreads();
        const int buf = t % STAGES;

#pragma unroll
        for (int ks = 0; ks < 2; ks++) {
            // A fragments: m16n8k16 layout — rows g/g+8, cols 2tq (+8), built from fp32 smem
            uint32_t afr[2][4];
#pragma unroll
            for (int mi = 0; mi < 2; mi++) {
                const float* r0 = &As[(buf * BM + wm * 32 + mi * 16 + g) * AKP + ks * 16];
                const float* r8 = r0 + 8 * AKP;
                float2 v0 = *reinterpret_cast<const float2*>(r0 + 2 * tq);
                float2 v1 = *reinterpret_cast<const float2*>(r8 + 2 * tq);
                float2 v2 = *reinterpret_cast<const float2*>(r0 + 2 * tq + 8);
                float2 v3 = *reinterpret_cast<const float2*>(r8 + 2 * tq + 8);
                afr[mi][0] = pack_h2(v0.x, v0.y);
                afr[mi][1] = pack_h2(v1.x, v1.y);
                afr[mi][2] = pack_h2(v2.x, v2.y);
                afr[mi][3] = pack_h2(v3.x, v3.y);
            }

            uint32_t bfr[NA][2];
#pragma unroll
            for (int ni2 = 0; ni2 < NA / 2; ni2++) {
                uint32_t tmp[4];
                ldm_x4_t(tmp, smem_u32(
                    &Bs[(buf * BK + ks * 16 + lb_k) * BNP + wn * WN + ni2 * 16 + lb_n]));
                bfr[2 * ni2][0]     = tmp[0];
                bfr[2 * ni2][1]     = tmp[1];
                bfr[2 * ni2 + 1][0] = tmp[2];
                bfr[2 * ni2 + 1][1] = tmp[3];
            }

#pragma unroll
            for (int mi = 0; mi < 2; mi++)
#pragma unroll
                for (int ni = 0; ni < NA; ni++)
                    mma_f16(acc[mi][ni], afr[mi], bfr[ni]);
        }

        int tn = t + STAGES - 1;
        if (tn < NT) issue(tn, tn % STAGES);
        asm volatile("cp.async.commit_group;" ::: "memory");
    }

#pragma unroll
    for (int mi = 0; mi < 2; mi++) {
        int rA = block_row + wm * 32 + mi * 16 + g;
        int rB = rA + 8;
        bool okA = rA < M, okB = rB < M;
#pragma unroll
        for (int ni = 0; ni < NA; ni++) {
            int col = wn * WN + ni * 8 + 2 * tq;
            if (okA)
                *reinterpret_cast<__half2*>(&H16[(size_t)rA * BN + col])
                    = __floats2half2_rn(acc[mi][ni][0], acc[mi][ni][1]);
            if (okB)
                *reinterpret_cast<__half2*>(&H16[(size_t)rB * BN + col])
                    = __floats2half2_rn(acc[mi][ni][2], acc[mi][ni][3]);
        }
    }
}

// ---------------- fp16 tensor-core GEMM (round-9 exact): BK=32, 3-stage ----------------
template<int BN, bool LAYER_EPI>
__global__ __launch_bounds__(256, 3) void k_gemm_tc(
    const __half* __restrict__ Ah, const __half* __restrict__ Wh,
    const float* __restrict__ bias, __half* __restrict__ H16,
    float* __restrict__ OUT, int M, int K)
{
    constexpr int BM = 128, BK = 32, STAGES = 3;
    constexpr int WN = BN / 2;
    constexpr int NA = WN / 8;
    constexpr int AKP = BK + 8;
    constexpr int BNP = BN + 8;
    constexpr int A_ST = BM * AKP;
    constexpr int BCH = BK * BN / 8;

    extern __shared__ __half smem[];
    __half* As = smem;
    __half* Bs = smem + STAGES * A_ST;

    const int tid  = threadIdx.x;
    const int wid  = tid >> 5;
    const int lane = tid & 31;
    const int g    = lane >> 2;
    const int tq   = lane & 3;
    const int wm   = wid & 3;
    const int wn   = wid >> 2;
    const int block_row = blockIdx.x * BM;

    float acc[2][NA][4];
#pragma unroll
    for (int mi = 0; mi < 2; mi++)
#pragma unroll
        for (int ni = 0; ni < NA; ni++)
#pragma unroll
            for (int q = 0; q < 4; q++) acc[mi][ni][q] = 0.0f;

    const int ar0 = tid >> 2,          ar1 = (tid + 256) >> 2;
    const int ac0 = (tid & 3) * 8,     ac1 = ((tid + 256) & 3) * 8;
    int grow0 = block_row + ar0; if (grow0 >= M) grow0 = M - 1;
    int grow1 = block_row + ar1; if (grow1 >= M) grow1 = M - 1;
    const __half* aSrc0 = Ah + (size_t)grow0 * K + ac0;
    const __half* aSrc1 = Ah + (size_t)grow1 * K + ac1;

    const int br0 = tid / (BN / 8),         bc0 = (tid % (BN / 8)) * 8;
    const int br1 = (tid + 256) / (BN / 8), bc1 = ((tid + 256) % (BN / 8)) * 8;

    auto issue = [&](int t, int buf) {
        int k0 = t * BK;
        cp16(smem_u32(&As[(buf * BM + ar0) * AKP + ac0]), aSrc0 + k0);
        cp16(smem_u32(&As[(buf * BM + ar1) * AKP + ac1]), aSrc1 + k0);
        cp16(smem_u32(&Bs[(buf * BK + br0) * BNP + bc0]),
             Wh + (size_t)(k0 + br0) * BN + bc0);
        if (256 < BCH && tid + 256 < BCH)
            cp16(smem_u32(&Bs[(buf * BK + br1) * BNP + bc1]),
                 Wh + (size_t)(k0 + br1) * BN + bc1);
    };

    const int NT = K / BK;
#pragma unroll
    for (int s = 0; s < STAGES - 1; s++) {
        issue(s, s);
        asm volatile("cp.async.commit_group;" ::: "memory");
    }

    const int la_r = (lane & 7) + ((lane >> 3) & 1) * 8;
    const int la_c = ((lane >> 4) & 1) * 8;
    const int lb_k = (lane & 7) + ((lane >> 3) & 1) * 8;
    const int lb_n = ((lane >> 4) & 1) * 8;

    for (int t = 0; t < NT; t++) {
        asm volatile("cp.async.wait_group %0;" :: "n"(STAGES - 2) : "memory");
        __syncthreads();
        const int buf = t % STAGES;

#pragma unroll
        for (int ks = 0; ks < 2; ks++) {
            uint32_t afr[2][4];
#pragma unroll
            for (int mi = 0; mi < 2; mi++)
                ldm_x4(afr[mi], smem_u32(
                    &As[(buf * BM + wm * 32 + mi * 16 + la_r) * AKP + ks * 16 + la_c]));

            uint32_t bfr[NA][2];
#pragma unroll
            for (int ni2 = 0; ni2 < NA / 2; ni2++) {
                uint32_t tmp[4];
                ldm_x4_t(tmp, smem_u32(
                    &Bs[(buf * BK + ks * 16 + lb_k) * BNP + wn * WN + ni2 * 16 + lb_n]));
                bfr[2 * ni2][0]     = tmp[0];
                bfr[2 * ni2][1]     = tmp[1];
                bfr[2 * ni2 + 1][0] = tmp[2];
                bfr[2 * ni2 + 1][1] = tmp[3];
            }

#pragma unroll
            for (int mi = 0; mi < 2; mi++)
#pragma unroll
                for (int ni = 0; ni < NA; ni++)
                    mma_f16(acc[mi][ni], afr[mi], bfr[ni]);
        }

        int tn = t + STAGES - 1;
        if (tn < NT) issue(tn, tn % STAGES);
        asm volatile("cp.async.commit_group;" ::: "memory");
    }

#pragma unroll
    for (int mi = 0; mi < 2; mi++) {
        int rA = block_row + wm * 32 + mi * 16 + g;
        int rB = rA + 8;
        bool okA = rA < M, okB = rB < M;
#pragma unroll
        for (int ni = 0; ni < NA; ni++) {
            int col = wn * WN + ni * 8 + 2 * tq;
            if (LAYER_EPI) {
                if (okA)
                    *reinterpret_cast<__half2*>(&H16[(size_t)rA * BN + col])
                        = __floats2half2_rn(acc[mi][ni][0], acc[mi][ni][1]);
                if (okB)
                    *reinterpret_cast<__half2*>(&H16[(size_t)rB * BN + col])
                        = __floats2half2_rn(acc[mi][ni][2], acc[mi][ni][3]);
            } else {
                float bx = bias[col], by = bias[col + 1];
                if (okA)
                    *reinterpret_cast<float2*>(&OUT[(size_t)rA * BN + col])
                        = make_float2(acc[mi][ni][0] + bx, acc[mi][ni][1] + by);
                if (okB)
                    *reinterpret_cast<float2*>(&OUT[(size_t)rB * BN + col])
                        = make_float2(acc[mi][ni][2] + bx, acc[mi][ni][3] + by);
            }
        }
    }
}

// ---------------- CSR gather + self-loop + bias + relu (round-9 exact) ----------------
__global__ __launch_bounds__(256) void k_gather(const float* __restrict__ bias) {
    int node = (blockIdx.x * 256 + threadIdx.x) >> 5;
    if (node >= N_NODES) return;
    int lane = threadIdx.x & 31;
    int beg = g_rowptr[node];
    int end = g_rowptr[node + 1];
    const bool active = lane < (HID / 4);
    const int coff = lane * 4;

    float4 acc = make_float4(0.f, 0.f, 0.f, 0.f);
#pragma unroll 4
    for (int e = beg; e < end; e++) {
        float2 ed = __ldg(&g_edge[e]);
        int s = __float_as_int(ed.x);
        float w = ed.y;
        if (active) {
            uint2 p = *reinterpret_cast<const uint2*>(&g_h16[(size_t)s * HID + coff]);
            float2 f0 = __half22float2(*reinterpret_cast<__half2*>(&p.x));
            float2 f1 = __half22float2(*reinterpret_cast<__half2*>(&p.y));
            acc.x = fmaf(f0.x, w, acc.x);
            acc.y = fmaf(f0.y, w, acc.y);
            acc.z = fmaf(f1.x, w, acc.z);
            acc.w = fmaf(f1.y, w, acc.w);
        }
    }
    if (active) {
        uint2 p = *reinterpret_cast<const uint2*>(&g_h16[(size_t)node * HID + coff]);
        float2 f0 = __half22float2(*reinterpret_cast<__half2*>(&p.x));
        float2 f1 = __half22float2(*reinterpret_cast<__half2*>(&p.y));
        float d = g_dinv[node];
        float dd = d * d;
        float4 b4 = *reinterpret_cast<const float4*>(&bias[coff]);
        float r0 = fmaxf(fmaf(f0.x, dd, acc.x) + b4.x, 0.f);
        float r1 = fmaxf(fmaf(f0.y, dd, acc.y) + b4.y, 0.f);
        float r2 = fmaxf(fmaf(f1.x, dd, acc.z) + b4.z, 0.f);
        float r3 = fmaxf(fmaf(f1.y, dd, acc.w) + b4.w, 0.f);
        st_half4(&g_a16[(size_t)node * HID + coff], make_float4(r0, r1, r2, r3));
    }
}

extern "C" void kernel_launch(void* const* d_in, const int* in_sizes, int n_in,
                              void* d_out, int out_size)
{
    const float* x    = (const float*)d_in[0];
    const int*   ei   = (const int*)d_in[1];
    const float* W0   = (const float*)d_in[2];
    const float* b0   = (const float*)d_in[3];
    const float* W1   = (const float*)d_in[4];
    const float* b1   = (const float*)d_in[5];
    const float* W2   = (const float*)d_in[6];
    const float* b2   = (const float*)d_in[7];
    const float* fcW  = (const float*)d_in[8];
    const float* fcb  = (const float*)d_in[9];
    float* out = (float*)d_out;

    const int* src = ei;
    const int* dst = ei + N_EDGES;

    __half* w16; cudaGetSymbolAddress((void**)&w16, g_w16);
    __half* h16; cudaGetSymbolAddress((void**)&h16, g_h16);
    __half* a16; cudaGetSymbolAddress((void**)&a16, g_a16);
    int*    deg; cudaGetSymbolAddress((void**)&deg, g_deg);

    constexpr int SMEM_96 = 3 * (128 * 40 + 32 * (HID + 8)) * 2;   // 50688
    constexpr int SMEM_64 = 3 * (128 * 40 + 32 * (OUTD + 8)) * 2;  // 44544
    constexpr int SMEM_G0 = 3 * (128 * 36) * 4 + 3 * (32 * (HID + 8)) * 2;  // 75264

    static cudaStream_t s2 = nullptr;
    static cudaEvent_t evFork = nullptr, evJoin = nullptr;
    if (!s2) {
        cudaStreamCreateWithFlags(&s2, cudaStreamNonBlocking);
        cudaEventCreateWithFlags(&evFork, cudaEventDisableTiming);
        cudaEventCreateWithFlags(&evJoin, cudaEventDisableTiming);
        cudaFuncSetAttribute(k_gemm_tc<HID, true>,
                             cudaFuncAttributeMaxDynamicSharedMemorySize, SMEM_96);
        cudaFuncSetAttribute(k_gemm_tc<OUTD, false>,
                             cudaFuncAttributeMaxDynamicSharedMemorySize, SMEM_64);
        cudaFuncSetAttribute(k_gemm0_f32,
                             cudaFuncAttributeMaxDynamicSharedMemorySize, SMEM_G0);
    }

    const int M = N_NODES;
    dim3 gemm_grid((M + 127) / 128);
    int gather_grid = (N_NODES * 32 + 255) / 256;

    // ---- launch 1: weight conversion on s2 (tiny) ----
    cudaEventRecord(evFork, 0);
    cudaStreamWaitEvent(s2, evFork, 0);
    k_cvt_w<<<(W16_TOT / 4 + 255) / 256, 256, 0, s2>>>(W0, W1, W2, fcW);

    // ---- degree + scan1 on main (launches 2,3) ----
    cudaMemsetAsync(deg, 0, N_NODES * sizeof(int), 0);
    k_count_deg<<<(N_EDGES + 255) / 256, 256>>>(dst);
    k_scan1<<<NBLK, SCAN_BS>>>();                 // also computes dinv

    // ---- launch 4 (profiled): GEMM0 on s2 reads fp32 x directly ----
    k_gemm0_f32<<<gemm_grid, 256, SMEM_G0, s2>>>(x, w16 + W16_W0, h16, M);
    cudaEventRecord(evJoin, s2);

    // ---- rest of CSR build on main, overlapped with GEMM0 ----
    k_scan2<<<1, 128>>>();
    k_scan3<<<(N_NODES + 255) / 256, 256>>>();
    k_fill<<<(N_EDGES + 255) / 256, 256>>>(src, dst);

    // ---- join, then layer pipeline ----
    cudaStreamWaitEvent(0, evJoin, 0);
    k_gather<<<gather_grid, 256>>>(b0);   // a16 = relu(agg0)

    k_gemm_tc<HID, true><<<gemm_grid, 256, SMEM_96>>>(
        a16, w16 + W16_W1, nullptr, h16, nullptr, M, HID);
    k_gather<<<gather_grid, 256>>>(b1);

    k_gemm_tc<HID, true><<<gemm_grid, 256, SMEM_96>>>(
        a16, w16 + W16_W2, nullptr, h16, nullptr, M, HID);
    k_gather<<<gather_grid, 256>>>(b2);

    // FC head: out = a16 @ fcW + fcb
    k_gemm_tc<OUTD, false><<<gemm_grid, 256, SMEM_64>>>(
        a16, w16 + W16_FC, fcb, nullptr, out, M, HID);
}

// round 15
// speedup vs baseline: 1.2648x; 1.0061x over previous
#include <cuda_runtime.h>
#include <cuda_fp16.h>
#include <cstdint>

#define N_NODES 50000
#define N_EDGES 800000
#define IN_DIM  512
#define HID     96
#define OUTD    64
#define SCAN_BS 512
#define NBLK    ((N_NODES + SCAN_BS - 1) / SCAN_BS)   // 98

// fp16 weight pool offsets (halves)
#define W16_W0  0
#define W16_W1  (IN_DIM * HID)
#define W16_W2  (W16_W1 + HID * HID)
#define W16_FC  (W16_W2 + HID * HID)
#define W16_TOT (W16_FC + HID * OUTD)

// Scratch (alloc-free rule: __device__ globals)
__device__ __align__(16) __half g_w16[W16_TOT];
__device__ __align__(16) __half g_h16[N_NODES * HID];   // GEMM out (gather input)
__device__ __align__(16) __half g_a16[N_NODES * HID];   // relu(agg) (next GEMM's A)
__device__ float  g_dinv[N_NODES];
__device__ int    g_deg[N_NODES];
__device__ int    g_rowptr[N_NODES + 1];
__device__ int    g_cursor[N_NODES];
__device__ int    g_bsum[128];
__device__ __align__(16) float2 g_edge[N_EDGES];        // (.x = src bits, .y = w)

// ---------------- fp32 -> fp16 helpers ----------------
__device__ __forceinline__ void st_half4(__half* p, float4 v) {
    __half2 a = __floats2half2_rn(v.x, v.y);
    __half2 b = __floats2half2_rn(v.z, v.w);
    uint2 u;
    u.x = *reinterpret_cast<uint32_t*>(&a);
    u.y = *reinterpret_cast<uint32_t*>(&b);
    *reinterpret_cast<uint2*>(p) = u;
}

// weights only (tiny; runs first on s2)
__global__ void k_cvt_w(const float* __restrict__ W0, const float* __restrict__ W1,
                        const float* __restrict__ W2, const float* __restrict__ fcW)
{
    constexpr int S0 = IN_DIM * HID / 4;
    constexpr int S1 = HID * HID / 4;
    constexpr int S3 = HID * OUTD / 4;
    int j = blockIdx.x * blockDim.x + threadIdx.x;
    const float* src; __half* dst;
    if (j < S0)                    { src = W0 + j * 4;               dst = &g_w16[W16_W0 + j * 4]; }
    else if (j < S0 + S1)          { j -= S0;  src = W1 + j * 4;     dst = &g_w16[W16_W1 + j * 4]; }
    else if (j < S0 + 2 * S1)      { j -= S0 + S1; src = W2 + j * 4; dst = &g_w16[W16_W2 + j * 4]; }
    else if (j < S0 + 2 * S1 + S3) { j -= S0 + 2 * S1; src = fcW + j * 4; dst = &g_w16[W16_FC + j * 4]; }
    else return;
    float4 v = *reinterpret_cast<const float4*>(src);
    st_half4(dst, v);
}

// ---------------- degree ----------------
__global__ void k_count_deg(const int* __restrict__ dst) {
    int e = blockIdx.x * blockDim.x + threadIdx.x;
    if (e < N_EDGES) atomicAdd(&g_deg[dst[e]], 1);
}

// ---------------- CSR build (scan1 also computes dinv) ----------------
__global__ __launch_bounds__(SCAN_BS) void k_scan1() {
    __shared__ int sh[2][SCAN_BS];
    int t = threadIdx.x;
    int i = blockIdx.x * SCAN_BS + t;
    int v = (i < N_NODES) ? g_deg[i] : 0;
    if (i < N_NODES) g_dinv[i] = rsqrtf((float)v + 1.0f);
    sh[0][t] = v;
    __syncthreads();
    int cur = 0;
#pragma unroll
    for (int off = 1; off < SCAN_BS; off <<= 1) {
        int x = sh[cur][t];
        if (t >= off) x += sh[cur][t - off];
        sh[cur ^ 1][t] = x;
        cur ^= 1;
        __syncthreads();
    }
    int incl = sh[cur][t];
    if (i < N_NODES) g_rowptr[i] = incl - v;
    if (t == SCAN_BS - 1) g_bsum[blockIdx.x] = incl;
}

__global__ void k_scan2() {
    __shared__ int sh[2][128];
    int t = threadIdx.x;
    int v = (t < NBLK) ? g_bsum[t] : 0;
    sh[0][t] = v;
    __syncthreads();
    int cur = 0;
#pragma unroll
    for (int off = 1; off < 128; off <<= 1) {
        int x = sh[cur][t];
        if (t >= off) x += sh[cur][t - off];
        sh[cur ^ 1][t] = x;
        cur ^= 1;
        __syncthreads();
    }
    if (t < NBLK) g_bsum[t] = sh[cur][t] - v;
}

__global__ void k_scan3() {
    int i = blockIdx.x * blockDim.x + threadIdx.x;
    if (i < N_NODES) {
        int r = g_rowptr[i] + g_bsum[i / SCAN_BS];
        g_rowptr[i] = r;
        g_cursor[i] = r;
    }
    if (i == 0) g_rowptr[N_NODES] = N_EDGES;
}

__global__ void k_fill(const int* __restrict__ src, const int* __restrict__ dst) {
    int e = blockIdx.x * blockDim.x + threadIdx.x;
    if (e >= N_EDGES) return;
    int s = src[e], d = dst[e];
    int pos = atomicAdd(&g_cursor[d], 1);
    g_edge[pos] = make_float2(__int_as_float(s), g_dinv[s] * g_dinv[d]);
}

// ---------------- MMA helpers ----------------
__device__ __forceinline__ uint32_t smem_u32(const void* p) {
    return (uint32_t)__cvta_generic_to_shared(p);
}

__device__ __forceinline__ void cp16(uint32_t dst, const void* src) {
    asm volatile("cp.async.cg.shared.global [%0], [%1], 16;" :: "r"(dst), "l"(src));
}

__device__ __forceinline__ void ldm_x4(uint32_t* d, uint32_t addr) {
    asm volatile("ldmatrix.sync.aligned.m8n8.x4.shared.b16 {%0,%1,%2,%3}, [%4];"
                 : "=r"(d[0]), "=r"(d[1]), "=r"(d[2]), "=r"(d[3]) : "r"(addr));
}

__device__ __forceinline__ void ldm_x4_t(uint32_t* d, uint32_t addr) {
    asm volatile("ldmatrix.sync.aligned.m8n8.x4.trans.shared.b16 {%0,%1,%2,%3}, [%4];"
                 : "=r"(d[0]), "=r"(d[1]), "=r"(d[2]), "=r"(d[3]) : "r"(addr));
}

__device__ __forceinline__ void mma_f16(float* c, const uint32_t* a, const uint32_t* b) {
    asm volatile(
        "mma.sync.aligned.m16n8k16.row.col.f32.f16.f16.f32 "
        "{%0,%1,%2,%3}, {%4,%5,%6,%7}, {%8,%9}, {%0,%1,%2,%3};"
        : "+f"(c[0]), "+f"(c[1]), "+f"(c[2]), "+f"(c[3])
        : "r"(a[0]), "r"(a[1]), "r"(a[2]), "r"(a[3]),
          "r"(b[0]), "r"(b[1]));
}

__device__ __forceinline__ uint32_t pack_h2(float lo, float hi) {
    __half2 h = __floats2half2_rn(lo, hi);
    return *reinterpret_cast<uint32_t*>(&h);
}

// ---------------- GEMM0 (fp32 A direct): h16 = half(x @ W0) ----------------
// A fp32 staged via cp.async; fragments built by direct smem float2 loads.
// AKP=40 floats: row stride mod 32 banks = 8 -> A-fragment LDS.64 loads are
// bank-conflict-free (g=0..3 rows hit disjoint bank groups per phase).
// smem 81.4KB -> 2 CTAs/SM; kernel is L1-throughput-bound so conflict removal
// dominates the occupancy loss.
__global__ __launch_bounds__(256, 2) void k_gemm0_f32(
    const float* __restrict__ A, const __half* __restrict__ Wh,
    __half* __restrict__ H16, int M)
{
    constexpr int BN = HID, K = IN_DIM;
    constexpr int BM = 128, BK = 32, STAGES = 3;
    constexpr int WN = BN / 2;        // 48
    constexpr int NA = WN / 8;        // 6
    constexpr int AKP = BK + 8;       // 40 floats (160B rows; stride mod 32 banks = 8)
    constexpr int BNP = BN + 8;       // 104 halves
    constexpr int A_ST = BM * AKP;    // floats per A stage
    constexpr int BCH = BK * BN / 8;  // 384 B-chunks per tile

    extern __shared__ float smemf[];
    float*  As = smemf;                                            // [STAGES][BM][AKP] fp32
    __half* Bs = reinterpret_cast<__half*>(smemf + STAGES * A_ST); // [STAGES][BK][BNP]

    const int tid  = threadIdx.x;
    const int wid  = tid >> 5;
    const int lane = tid & 31;
    const int g    = lane >> 2;
    const int tq   = lane & 3;
    const int wm   = wid & 3;
    const int wn   = wid >> 2;
    const int block_row = blockIdx.x * BM;

    float acc[2][NA][4];
#pragma unroll
    for (int mi = 0; mi < 2; mi++)
#pragma unroll
        for (int ni = 0; ni < NA; ni++)
#pragma unroll
            for (int q = 0; q < 4; q++) acc[mi][ni][q] = 0.0f;

    // A: 128 rows x 8 chunks (16B = 4 floats) = 1024 chunks -> 4 per thread
    int arow[4], acol[4];
    const float* asrc[4];
#pragma unroll
    for (int i = 0; i < 4; i++) {
        int j = tid + i * 256;
        arow[i] = j >> 3;
        acol[i] = (j & 7) * 4;
        int grow = block_row + arow[i]; if (grow >= M) grow = M - 1;  // row-clamp safe
        asrc[i] = A + (size_t)grow * K + acol[i];
    }

    const int br0 = tid / (BN / 8),         bc0 = (tid % (BN / 8)) * 8;
    const int br1 = (tid + 256) / (BN / 8), bc1 = ((tid + 256) % (BN / 8)) * 8;

    auto issue = [&](int t, int buf) {
        int k0 = t * BK;
#pragma unroll
        for (int i = 0; i < 4; i++)
            cp16(smem_u32(&As[(buf * BM + arow[i]) * AKP + acol[i]]), asrc[i] + k0);
        cp16(smem_u32(&Bs[(buf * BK + br0) * BNP + bc0]),
             Wh + (size_t)(k0 + br0) * BN + bc0);
        if (tid + 256 < BCH)
            cp16(smem_u32(&Bs[(buf * BK + br1) * BNP + bc1]),
                 Wh + (size_t)(k0 + br1) * BN + bc1);
    };

    const int NT = K / BK;   // 16
#pragma unroll
    for (int s = 0; s < STAGES - 1; s++) {
        issue(s, s);
        asm volatile("cp.async.commit_group;" ::: "memory");
    }

    const int lb_k = (lane & 7) + ((lane >> 3) & 1) * 8;
    const int lb_n = ((lane >> 4) & 1) * 8;

    for (int t = 0; t < NT; t++) {
        asm volatile("cp.async.wait_group %0;" :: "n"(STAGES - 2) : "memory");
        __syncthreads();
        const int buf = t % STAGES;

#pragma unroll
        for (int ks = 0; ks < 2; ks++) {
            // A fragments: m16n8k16 layout — rows g/g+8, cols 2tq (+8), from fp32 smem
            uint32_t afr[2][4];
#pragma unroll
            for (int mi = 0; mi < 2; mi++) {
                const float* r0 = &As[(buf * BM + wm * 32 + mi * 16 + g) * AKP + ks * 16];
                const float* r8 = r0 + 8 * AKP;
                float2 v0 = *reinterpret_cast<const float2*>(r0 + 2 * tq);
                float2 v1 = *reinterpret_cast<const float2*>(r8 + 2 * tq);
                float2 v2 = *reinterpret_cast<const float2*>(r0 + 2 * tq + 8);
                float2 v3 = *reinterpret_cast<const float2*>(r8 + 2 * tq + 8);
                afr[mi][0] = pack_h2(v0.x, v0.y);
                afr[mi][1] = pack_h2(v1.x, v1.y);
                afr[mi][2] = pack_h2(v2.x, v2.y);
                afr[mi][3] = pack_h2(v3.x, v3.y);
            }

            uint32_t bfr[NA][2];
#pragma unroll
            for (int ni2 = 0; ni2 < NA / 2; ni2++) {
                uint32_t tmp[4];
                ldm_x4_t(tmp, smem_u32(
                    &Bs[(buf * BK + ks * 16 + lb_k) * BNP + wn * WN + ni2 * 16 + lb_n]));
                bfr[2 * ni2][0]     = tmp[0];
                bfr[2 * ni2][1]     = tmp[1];
                bfr[2 * ni2 + 1][0] = tmp[2];
                bfr[2 * ni2 + 1][1] = tmp[3];
            }

#pragma unroll
            for (int mi = 0; mi < 2; mi++)
#pragma unroll
                for (int ni = 0; ni < NA; ni++)
                    mma_f16(acc[mi][ni], afr[mi], bfr[ni]);
        }

        int tn = t + STAGES - 1;
        if (tn < NT) issue(tn, tn % STAGES);
        asm volatile("cp.async.commit_group;" ::: "memory");
    }

#pragma unroll
    for (int mi = 0; mi < 2; mi++) {
        int rA = block_row + wm * 32 + mi * 16 + g;
        int rB = rA + 8;
        bool okA = rA < M, okB = rB < M;
#pragma unroll
        for (int ni = 0; ni < NA; ni++) {
            int col = wn * WN + ni * 8 + 2 * tq;
            if (okA)
                *reinterpret_cast<__half2*>(&H16[(size_t)rA * BN + col])
                    = __floats2half2_rn(acc[mi][ni][0], acc[mi][ni][1]);
            if (okB)
                *reinterpret_cast<__half2*>(&H16[(size_t)rB * BN + col])
                    = __floats2half2_rn(acc[mi][ni][2], acc[mi][ni][3]);
        }
    }
}

// ---------------- fp16 tensor-core GEMM (round-9 exact): BK=32, 3-stage ----------------
template<int BN, bool LAYER_EPI>
__global__ __launch_bounds__(256, 3) void k_gemm_tc(
    const __half* __restrict__ Ah, const __half* __restrict__ Wh,
    const float* __restrict__ bias, __half* __restrict__ H16,
    float* __restrict__ OUT, int M, int K)
{
    constexpr int BM = 128, BK = 32, STAGES = 3;
    constexpr int WN = BN / 2;
    constexpr int NA = WN / 8;
    constexpr int AKP = BK + 8;
    constexpr int BNP = BN + 8;
    constexpr int A_ST = BM * AKP;
    constexpr int BCH = BK * BN / 8;

    extern __shared__ __half smem[];
    __half* As = smem;
    __half* Bs = smem + STAGES * A_ST;

    const int tid  = threadIdx.x;
    const int wid  = tid >> 5;
    const int lane = tid & 31;
    const int g    = lane >> 2;
    const int tq   = lane & 3;
    const int wm   = wid & 3;
    const int wn   = wid >> 2;
    const int block_row = blockIdx.x * BM;

    float acc[2][NA][4];
#pragma unroll
    for (int mi = 0; mi < 2; mi++)
#pragma unroll
        for (int ni = 0; ni < NA; ni++)
#pragma unroll
            for (int q = 0; q < 4; q++) acc[mi][ni][q] = 0.0f;

    const int ar0 = tid >> 2,          ar1 = (tid + 256) >> 2;
    const int ac0 = (tid & 3) * 8,     ac1 = ((tid + 256) & 3) * 8;
    int grow0 = block_row + ar0; if (grow0 >= M) grow0 = M - 1;
    int grow1 = block_row + ar1; if (grow1 >= M) grow1 = M - 1;
    const __half* aSrc0 = Ah + (size_t)grow0 * K + ac0;
    const __half* aSrc1 = Ah + (size_t)grow1 * K + ac1;

    const int br0 = tid / (BN / 8),         bc0 = (tid % (BN / 8)) * 8;
    const int br1 = (tid + 256) / (BN / 8), bc1 = ((tid + 256) % (BN / 8)) * 8;

    auto issue = [&](int t, int buf) {
        int k0 = t * BK;
        cp16(smem_u32(&As[(buf * BM + ar0) * AKP + ac0]), aSrc0 + k0);
        cp16(smem_u32(&As[(buf * BM + ar1) * AKP + ac1]), aSrc1 + k0);
        cp16(smem_u32(&Bs[(buf * BK + br0) * BNP + bc0]),
             Wh + (size_t)(k0 + br0) * BN + bc0);
        if (256 < BCH && tid + 256 < BCH)
            cp16(smem_u32(&Bs[(buf * BK + br1) * BNP + bc1]),
                 Wh + (size_t)(k0 + br1) * BN + bc1);
    };

    const int NT = K / BK;
#pragma unroll
    for (int s = 0; s < STAGES - 1; s++) {
        issue(s, s);
        asm volatile("cp.async.commit_group;" ::: "memory");
    }

    const int la_r = (lane & 7) + ((lane >> 3) & 1) * 8;
    const int la_c = ((lane >> 4) & 1) * 8;
    const int lb_k = (lane & 7) + ((lane >> 3) & 1) * 8;
    const int lb_n = ((lane >> 4) & 1) * 8;

    for (int t = 0; t < NT; t++) {
        asm volatile("cp.async.wait_group %0;" :: "n"(STAGES - 2) : "memory");
        __syncthreads();
        const int buf = t % STAGES;

#pragma unroll
        for (int ks = 0; ks < 2; ks++) {
            uint32_t afr[2][4];
#pragma unroll
            for (int mi = 0; mi < 2; mi++)
                ldm_x4(afr[mi], smem_u32(
                    &As[(buf * BM + wm * 32 + mi * 16 + la_r) * AKP + ks * 16 + la_c]));

            uint32_t bfr[NA][2];
#pragma unroll
            for (int ni2 = 0; ni2 < NA / 2; ni2++) {
                uint32_t tmp[4];
                ldm_x4_t(tmp, smem_u32(
                    &Bs[(buf * BK + ks * 16 + lb_k) * BNP + wn * WN + ni2 * 16 + lb_n]));
                bfr[2 * ni2][0]     = tmp[0];
                bfr[2 * ni2][1]     = tmp[1];
                bfr[2 * ni2 + 1][0] = tmp[2];
                bfr[2 * ni2 + 1][1] = tmp[3];
            }

#pragma unroll
            for (int mi = 0; mi < 2; mi++)
#pragma unroll
                for (int ni = 0; ni < NA; ni++)
                    mma_f16(acc[mi][ni], afr[mi], bfr[ni]);
        }

        int tn = t + STAGES - 1;
        if (tn < NT) issue(tn, tn % STAGES);
        asm volatile("cp.async.commit_group;" ::: "memory");
    }

#pragma unroll
    for (int mi = 0; mi < 2; mi++) {
        int rA = block_row + wm * 32 + mi * 16 + g;
        int rB = rA + 8;
        bool okA = rA < M, okB = rB < M;
#pragma unroll
        for (int ni = 0; ni < NA; ni++) {
            int col = wn * WN + ni * 8 + 2 * tq;
            if (LAYER_EPI) {
                if (okA)
                    *reinterpret_cast<__half2*>(&H16[(size_t)rA * BN + col])
                        = __floats2half2_rn(acc[mi][ni][0], acc[mi][ni][1]);
                if (okB)
                    *reinterpret_cast<__half2*>(&H16[(size_t)rB * BN + col])
                        = __floats2half2_rn(acc[mi][ni][2], acc[mi][ni][3]);
            } else {
                float bx = bias[col], by = bias[col + 1];
                if (okA)
                    *reinterpret_cast<float2*>(&OUT[(size_t)rA * BN + col])
                        = make_float2(acc[mi][ni][0] + bx, acc[mi][ni][1] + by);
                if (okB)
                    *reinterpret_cast<float2*>(&OUT[(size_t)rB * BN + col])
                        = make_float2(acc[mi][ni][2] + bx, acc[mi][ni][3] + by);
            }
        }
    }
}

// ---------------- CSR gather + self-loop + bias + relu ----------------
// Round-9 proven loop; edge records loaded with evict-first (.cs) so the
// zero-reuse edge stream doesn't evict reused h16 rows from L1.
__global__ __launch_bounds__(256) void k_gather(const float* __restrict__ bias) {
    int node = (blockIdx.x * 256 + threadIdx.x) >> 5;
    if (node >= N_NODES) return;
    int lane = threadIdx.x & 31;
    int beg = g_rowptr[node];
    int end = g_rowptr[node + 1];
    const bool active = lane < (HID / 4);
    const int coff = lane * 4;

    float4 acc = make_float4(0.f, 0.f, 0.f, 0.f);
#pragma unroll 4
    for (int e = beg; e < end; e++) {
        float2 ed = __ldcs(&g_edge[e]);   // streamed, evict-first
        int s = __float_as_int(ed.x);
        float w = ed.y;
        if (active) {
            uint2 p = *reinterpret_cast<const uint2*>(&g_h16[(size_t)s * HID + coff]);
            float2 f0 = __half22float2(*reinterpret_cast<__half2*>(&p.x));
            float2 f1 = __half22float2(*reinterpret_cast<__half2*>(&p.y));
            acc.x = fmaf(f0.x, w, acc.x);
            acc.y = fmaf(f0.y, w, acc.y);
            acc.z = fmaf(f1.x, w, acc.z);
            acc.w = fmaf(f1.y, w, acc.w);
        }
    }
    if (active) {
        uint2 p = *reinterpret_cast<const uint2*>(&g_h16[(size_t)node * HID + coff]);
        float2 f0 = __half22float2(*reinterpret_cast<__half2*>(&p.x));
        float2 f1 = __half22float2(*reinterpret_cast<__half2*>(&p.y));
        float d = g_dinv[node];
        float dd = d * d;
        float4 b4 = *reinterpret_cast<const float4*>(&bias[coff]);
        float r0 = fmaxf(fmaf(f0.x, dd, acc.x) + b4.x, 0.f);
        float r1 = fmaxf(fmaf(f0.y, dd, acc.y) + b4.y, 0.f);
        float r2 = fmaxf(fmaf(f1.x, dd, acc.z) + b4.z, 0.f);
        float r3 = fmaxf(fmaf(f1.y, dd, acc.w) + b4.w, 0.f);
        st_half4(&g_a16[(size_t)node * HID + coff], make_float4(r0, r1, r2, r3));
    }
}

extern "C" void kernel_launch(void* const* d_in, const int* in_sizes, int n_in,
                              void* d_out, int out_size)
{
    const float* x    = (const float*)d_in[0];
    const int*   ei   = (const int*)d_in[1];
    const float* W0   = (const float*)d_in[2];
    const float* b0   = (const float*)d_in[3];
    const float* W1   = (const float*)d_in[4];
    const float* b1   = (const float*)d_in[5];
    const float* W2   = (const float*)d_in[6];
    const float* b2   = (const float*)d_in[7];
    const float* fcW  = (const float*)d_in[8];
    const float* fcb  = (const float*)d_in[9];
    float* out = (float*)d_out;

    const int* src = ei;
    const int* dst = ei + N_EDGES;

    __half* w16; cudaGetSymbolAddress((void**)&w16, g_w16);
    __half* h16; cudaGetSymbolAddress((void**)&h16, g_h16);
    __half* a16; cudaGetSymbolAddress((void**)&a16, g_a16);
    int*    deg; cudaGetSymbolAddress((void**)&deg, g_deg);

    constexpr int SMEM_96 = 3 * (128 * 40 + 32 * (HID + 8)) * 2;   // 50688
    constexpr int SMEM_64 = 3 * (128 * 40 + 32 * (OUTD + 8)) * 2;  // 44544
    constexpr int SMEM_G0 = 3 * (128 * 40) * 4 + 3 * (32 * (HID + 8)) * 2;  // 81408

    static cudaStream_t s2 = nullptr;
    static cudaEvent_t evFork = nullptr, evJoin = nullptr;
    if (!s2) {
        cudaStreamCreateWithFlags(&s2, cudaStreamNonBlocking);
        cudaEventCreateWithFlags(&evFork, cudaEventDisableTiming);
        cudaEventCreateWithFlags(&evJoin, cudaEventDisableTiming);
        cudaFuncSetAttribute(k_gemm_tc<HID, true>,
                             cudaFuncAttributeMaxDynamicSharedMemorySize, SMEM_96);
        cudaFuncSetAttribute(k_gemm_tc<OUTD, false>,
                             cudaFuncAttributeMaxDynamicSharedMemorySize, SMEM_64);
        cudaFuncSetAttribute(k_gemm0_f32,
                             cudaFuncAttributeMaxDynamicSharedMemorySize, SMEM_G0);
    }

    const int M = N_NODES;
    dim3 gemm_grid((M + 127) / 128);
    int gather_grid = (N_NODES * 32 + 255) / 256;

    // ---- launch 1: weight conversion on s2 (tiny) ----
    cudaEventRecord(evFork, 0);
    cudaStreamWaitEvent(s2, evFork, 0);
    k_cvt_w<<<(W16_TOT / 4 + 255) / 256, 256, 0, s2>>>(W0, W1, W2, fcW);

    // ---- degree + scan1 on main ----
    cudaMemsetAsync(deg, 0, N_NODES * sizeof(int), 0);
    k_count_deg<<<(N_EDGES + 255) / 256, 256>>>(dst);
    k_scan1<<<NBLK, SCAN_BS>>>();                 // also computes dinv

    // ---- GEMM0 on s2 reads fp32 x directly (profiled slot) ----
    k_gemm0_f32<<<gemm_grid, 256, SMEM_G0, s2>>>(x, w16 + W16_W0, h16, M);
    cudaEventRecord(evJoin, s2);

    // ---- rest of CSR build on main, overlapped with GEMM0 ----
    k_scan2<<<1, 128>>>();
    k_scan3<<<(N_NODES + 255) / 256, 256>>>();
    k_fill<<<(N_EDGES + 255) / 256, 256>>>(src, dst);

    // ---- join, then layer pipeline ----
    cudaStreamWaitEvent(0, evJoin, 0);
    k_gather<<<gather_grid, 256>>>(b0);   // a16 = relu(agg0)

    k_gemm_tc<HID, true><<<gemm_grid, 256, SMEM_96>>>(
        a16, w16 + W16_W1, nullptr, h16, nullptr, M, HID);
    k_gather<<<gather_grid, 256>>>(b1);

    k_gemm_tc<HID, true><<<gemm_grid, 256, SMEM_96>>>(
        a16, w16 + W16_W2, nullptr, h16, nullptr, M, HID);
    k_gather<<<gather_grid, 256>>>(b2);

    // FC head: out = a16 @ fcW + fcb
    k_gemm_tc<OUTD, false><<<gemm_grid, 256, SMEM_64>>>(
        a16, w16 + W16_FC, fcb, nullptr, out, M, HID);
}

// round 16
// speedup vs baseline: 1.2733x; 1.0068x over previous
#include <cuda_runtime.h>
#include <cuda_fp16.h>
#include <cstdint>

#define N_NODES 50000
#define N_EDGES 800000
#define IN_DIM  512
#define HID     96
#define OUTD    64
#define SCAN_BS 512
#define NBLK    ((N_NODES + SCAN_BS - 1) / SCAN_BS)   // 98

// fp16 weight pool offsets (halves)
#define W16_W0  0
#define W16_W1  (IN_DIM * HID)
#define W16_W2  (W16_W1 + HID * HID)
#define W16_FC  (W16_W2 + HID * HID)
#define W16_TOT (W16_FC + HID * OUTD)

// Scratch (alloc-free rule: __device__ globals)
__device__ __align__(16) __half g_w16[W16_TOT];
__device__ __align__(16) __half g_h16[N_NODES * HID];   // GEMM out (gather input)
__device__ __align__(16) __half g_a16[N_NODES * HID];   // relu(agg) (next GEMM's A)
__device__ float  g_dinv[N_NODES];
__device__ int    g_deg[N_NODES];
__device__ int    g_rowptr[N_NODES + 1];
__device__ int    g_cursor[N_NODES];
__device__ int    g_bsum[128];
__device__ __align__(16) float2 g_edge[N_EDGES];        // (.x = src bits, .y = w)

// ---------------- fp32 -> fp16 helpers ----------------
__device__ __forceinline__ void st_half4(__half* p, float4 v) {
    __half2 a = __floats2half2_rn(v.x, v.y);
    __half2 b = __floats2half2_rn(v.z, v.w);
    uint2 u;
    u.x = *reinterpret_cast<uint32_t*>(&a);
    u.y = *reinterpret_cast<uint32_t*>(&b);
    *reinterpret_cast<uint2*>(p) = u;
}

// weights only (tiny; runs first on s2)
__global__ void k_cvt_w(const float* __restrict__ W0, const float* __restrict__ W1,
                        const float* __restrict__ W2, const float* __restrict__ fcW)
{
    constexpr int S0 = IN_DIM * HID / 4;
    constexpr int S1 = HID * HID / 4;
    constexpr int S3 = HID * OUTD / 4;
    int j = blockIdx.x * blockDim.x + threadIdx.x;
    const float* src; __half* dst;
    if (j < S0)                    { src = W0 + j * 4;               dst = &g_w16[W16_W0 + j * 4]; }
    else if (j < S0 + S1)          { j -= S0;  src = W1 + j * 4;     dst = &g_w16[W16_W1 + j * 4]; }
    else if (j < S0 + 2 * S1)      { j -= S0 + S1; src = W2 + j * 4; dst = &g_w16[W16_W2 + j * 4]; }
    else if (j < S0 + 2 * S1 + S3) { j -= S0 + 2 * S1; src = fcW + j * 4; dst = &g_w16[W16_FC + j * 4]; }
    else return;
    float4 v = *reinterpret_cast<const float4*>(src);
    st_half4(dst, v);
}

// ---------------- degree ----------------
__global__ void k_count_deg(const int* __restrict__ dst) {
    int e = blockIdx.x * blockDim.x + threadIdx.x;
    if (e < N_EDGES) atomicAdd(&g_deg[dst[e]], 1);
}

// ---------------- CSR build (scan1 also computes dinv) ----------------
__global__ __launch_bounds__(SCAN_BS) void k_scan1() {
    __shared__ int sh[2][SCAN_BS];
    int t = threadIdx.x;
    int i = blockIdx.x * SCAN_BS + t;
    int v = (i < N_NODES) ? g_deg[i] : 0;
    if (i < N_NODES) g_dinv[i] = rsqrtf((float)v + 1.0f);
    sh[0][t] = v;
    __syncthreads();
    int cur = 0;
#pragma unroll
    for (int off = 1; off < SCAN_BS; off <<= 1) {
        int x = sh[cur][t];
        if (t >= off) x += sh[cur][t - off];
        sh[cur ^ 1][t] = x;
        cur ^= 1;
        __syncthreads();
    }
    int incl = sh[cur][t];
    if (i < N_NODES) g_rowptr[i] = incl - v;
    if (t == SCAN_BS - 1) g_bsum[blockIdx.x] = incl;
}

__global__ void k_scan2() {
    __shared__ int sh[2][128];
    int t = threadIdx.x;
    int v = (t < NBLK) ? g_bsum[t] : 0;
    sh[0][t] = v;
    __syncthreads();
    int cur = 0;
#pragma unroll
    for (int off = 1; off < 128; off <<= 1) {
        int x = sh[cur][t];
        if (t >= off) x += sh[cur][t - off];
        sh[cur ^ 1][t] = x;
        cur ^= 1;
        __syncthreads();
    }
    if (t < NBLK) g_bsum[t] = sh[cur][t] - v;
}

__global__ void k_scan3() {
    int i = blockIdx.x * blockDim.x + threadIdx.x;
    if (i < N_NODES) {
        int r = g_rowptr[i] + g_bsum[i / SCAN_BS];
        g_rowptr[i] = r;
        g_cursor[i] = r;
    }
    if (i == 0) g_rowptr[N_NODES] = N_EDGES;
}

__global__ void k_fill(const int* __restrict__ src, const int* __restrict__ dst) {
    int e = blockIdx.x * blockDim.x + threadIdx.x;
    if (e >= N_EDGES) return;
    int s = src[e], d = dst[e];
    int pos = atomicAdd(&g_cursor[d], 1);
    g_edge[pos] = make_float2(__int_as_float(s), g_dinv[s] * g_dinv[d]);
}

// ---------------- MMA helpers ----------------
__device__ __forceinline__ uint32_t smem_u32(const void* p) {
    return (uint32_t)__cvta_generic_to_shared(p);
}

__device__ __forceinline__ void cp16(uint32_t dst, const void* src) {
    asm volatile("cp.async.cg.shared.global [%0], [%1], 16;" :: "r"(dst), "l"(src));
}

__device__ __forceinline__ void ldm_x4(uint32_t* d, uint32_t addr) {
    asm volatile("ldmatrix.sync.aligned.m8n8.x4.shared.b16 {%0,%1,%2,%3}, [%4];"
                 : "=r"(d[0]), "=r"(d[1]), "=r"(d[2]), "=r"(d[3]) : "r"(addr));
}

__device__ __forceinline__ void ldm_x4_t(uint32_t* d, uint32_t addr) {
    asm volatile("ldmatrix.sync.aligned.m8n8.x4.trans.shared.b16 {%0,%1,%2,%3}, [%4];"
                 : "=r"(d[0]), "=r"(d[1]), "=r"(d[2]), "=r"(d[3]) : "r"(addr));
}

__device__ __forceinline__ void mma_f16(float* c, const uint32_t* a, const uint32_t* b) {
    asm volatile(
        "mma.sync.aligned.m16n8k16.row.col.f32.f16.f16.f32 "
        "{%0,%1,%2,%3}, {%4,%5,%6,%7}, {%8,%9}, {%0,%1,%2,%3};"
        : "+f"(c[0]), "+f"(c[1]), "+f"(c[2]), "+f"(c[3])
        : "r"(a[0]), "r"(a[1]), "r"(a[2]), "r"(a[3]),
          "r"(b[0]), "r"(b[1]));
}

__device__ __forceinline__ uint32_t pack_h2(float lo, float hi) {
    __half2 h = __floats2half2_rn(lo, hi);
    return *reinterpret_cast<uint32_t*>(&h);
}

// ---------------- GEMM0 (fp32 A direct): h16 = half(x @ W0) ----------------
// A fp32 staged via cp.async; fragments from direct smem float2 loads (AKP=40:
// conflict-free). STAGES=4 -> 3 tiles in flight per CTA (6/SM at 2 CTAs):
// deeper MLP for the DRAM-bound x stream.
__global__ __launch_bounds__(256, 2) void k_gemm0_f32(
    const float* __restrict__ A, const __half* __restrict__ Wh,
    __half* __restrict__ H16, int M)
{
    constexpr int BN = HID, K = IN_DIM;
    constexpr int BM = 128, BK = 32, STAGES = 4;
    constexpr int WN = BN / 2;        // 48
    constexpr int NA = WN / 8;        // 6
    constexpr int AKP = BK + 8;       // 40 floats (160B rows; bank-conflict-free)
    constexpr int BNP = BN + 8;       // 104 halves
    constexpr int A_ST = BM * AKP;    // floats per A stage
    constexpr int BCH = BK * BN / 8;  // 384 B-chunks per tile

    extern __shared__ float smemf[];
    float*  As = smemf;                                            // [STAGES][BM][AKP] fp32
    __half* Bs = reinterpret_cast<__half*>(smemf + STAGES * A_ST); // [STAGES][BK][BNP]

    const int tid  = threadIdx.x;
    const int wid  = tid >> 5;
    const int lane = tid & 31;
    const int g    = lane >> 2;
    const int tq   = lane & 3;
    const int wm   = wid & 3;
    const int wn   = wid >> 2;
    const int block_row = blockIdx.x * BM;

    float acc[2][NA][4];
#pragma unroll
    for (int mi = 0; mi < 2; mi++)
#pragma unroll
        for (int ni = 0; ni < NA; ni++)
#pragma unroll
            for (int q = 0; q < 4; q++) acc[mi][ni][q] = 0.0f;

    // A: 128 rows x 8 chunks (16B = 4 floats) = 1024 chunks -> 4 per thread
    int arow[4], acol[4];
    const float* asrc[4];
#pragma unroll
    for (int i = 0; i < 4; i++) {
        int j = tid + i * 256;
        arow[i] = j >> 3;
        acol[i] = (j & 7) * 4;
        int grow = block_row + arow[i]; if (grow >= M) grow = M - 1;  // row-clamp safe
        asrc[i] = A + (size_t)grow * K + acol[i];
    }

    const int br0 = tid / (BN / 8),         bc0 = (tid % (BN / 8)) * 8;
    const int br1 = (tid + 256) / (BN / 8), bc1 = ((tid + 256) % (BN / 8)) * 8;

    auto issue = [&](int t, int buf) {
        int k0 = t * BK;
#pragma unroll
        for (int i = 0; i < 4; i++)
            cp16(smem_u32(&As[(buf * BM + arow[i]) * AKP + acol[i]]), asrc[i] + k0);
        cp16(smem_u32(&Bs[(buf * BK + br0) * BNP + bc0]),
             Wh + (size_t)(k0 + br0) * BN + bc0);
        if (tid + 256 < BCH)
            cp16(smem_u32(&Bs[(buf * BK + br1) * BNP + bc1]),
                 Wh + (size_t)(k0 + br1) * BN + bc1);
    };

    const int NT = K / BK;   // 16
#pragma unroll
    for (int s = 0; s < STAGES - 1; s++) {
        issue(s, s);
        asm volatile("cp.async.commit_group;" ::: "memory");
    }

    const int lb_k = (lane & 7) + ((lane >> 3) & 1) * 8;
    const int lb_n = ((lane >> 4) & 1) * 8;

    for (int t = 0; t < NT; t++) {
        asm volatile("cp.async.wait_group %0;" :: "n"(STAGES - 2) : "memory");
        __syncthreads();
        const int buf = t % STAGES;

#pragma unroll
        for (int ks = 0; ks < 2; ks++) {
            // A fragments: m16n8k16 layout — rows g/g+8, cols 2tq (+8), from fp32 smem
            uint32_t afr[2][4];
#pragma unroll
            for (int mi = 0; mi < 2; mi++) {
                const float* r0 = &As[(buf * BM + wm * 32 + mi * 16 + g) * AKP + ks * 16];
                const float* r8 = r0 + 8 * AKP;
                float2 v0 = *reinterpret_cast<const float2*>(r0 + 2 * tq);
                float2 v1 = *reinterpret_cast<const float2*>(r8 + 2 * tq);
                float2 v2 = *reinterpret_cast<const float2*>(r0 + 2 * tq + 8);
                float2 v3 = *reinterpret_cast<const float2*>(r8 + 2 * tq + 8);
                afr[mi][0] = pack_h2(v0.x, v0.y);
                afr[mi][1] = pack_h2(v1.x, v1.y);
                afr[mi][2] = pack_h2(v2.x, v2.y);
                afr[mi][3] = pack_h2(v3.x, v3.y);
            }

            uint32_t bfr[NA][2];
#pragma unroll
            for (int ni2 = 0; ni2 < NA / 2; ni2++) {
                uint32_t tmp[4];
                ldm_x4_t(tmp, smem_u32(
                    &Bs[(buf * BK + ks * 16 + lb_k) * BNP + wn * WN + ni2 * 16 + lb_n]));
                bfr[2 * ni2][0]     = tmp[0];
                bfr[2 * ni2][1]     = tmp[1];
                bfr[2 * ni2 + 1][0] = tmp[2];
                bfr[2 * ni2 + 1][1] = tmp[3];
            }

#pragma unroll
            for (int mi = 0; mi < 2; mi++)
#pragma unroll
                for (int ni = 0; ni < NA; ni++)
                    mma_f16(acc[mi][ni], afr[mi], bfr[ni]);
        }

        int tn = t + STAGES - 1;
        if (tn < NT) issue(tn, tn % STAGES);
        asm volatile("cp.async.commit_group;" ::: "memory");
    }

#pragma unroll
    for (int mi = 0; mi < 2; mi++) {
        int rA = block_row + wm * 32 + mi * 16 + g;
        int rB = rA + 8;
        bool okA = rA < M, okB = rB < M;
#pragma unroll
        for (int ni = 0; ni < NA; ni++) {
            int col = wn * WN + ni * 8 + 2 * tq;
            if (okA)
                *reinterpret_cast<__half2*>(&H16[(size_t)rA * BN + col])
                    = __floats2half2_rn(acc[mi][ni][0], acc[mi][ni][1]);
            if (okB)
                *reinterpret_cast<__half2*>(&H16[(size_t)rB * BN + col])
                    = __floats2half2_rn(acc[mi][ni][2], acc[mi][ni][3]);
        }
    }
}

// ---------------- fp16 tensor-core GEMM (known-good): BK=32, 3-stage ----------------
template<int BN, bool LAYER_EPI>
__global__ __launch_bounds__(256, 3) void k_gemm_tc(
    const __half* __restrict__ Ah, const __half* __restrict__ Wh,
    const float* __restrict__ bias, __half* __restrict__ H16,
    float* __restrict__ OUT, int M, int K)
{
    constexpr int BM = 128, BK = 32, STAGES = 3;
    constexpr int WN = BN / 2;
    constexpr int NA = WN / 8;
    constexpr int AKP = BK + 8;
    constexpr int BNP = BN + 8;
    constexpr int A_ST = BM * AKP;
    constexpr int BCH = BK * BN / 8;

    extern __shared__ __half smem[];
    __half* As = smem;
    __half* Bs = smem + STAGES * A_ST;

    const int tid  = threadIdx.x;
    const int wid  = tid >> 5;
    const int lane = tid & 31;
    const int g    = lane >> 2;
    const int tq   = lane & 3;
    const int wm   = wid & 3;
    const int wn   = wid >> 2;
    const int block_row = blockIdx.x * BM;

    float acc[2][NA][4];
#pragma unroll
    for (int mi = 0; mi < 2; mi++)
#pragma unroll
        for (int ni = 0; ni < NA; ni++)
#pragma unroll
            for (int q = 0; q < 4; q++) acc[mi][ni][q] = 0.0f;

    const int ar0 = tid >> 2,          ar1 = (tid + 256) >> 2;
    const int ac0 = (tid & 3) * 8,     ac1 = ((tid + 256) & 3) * 8;
    int grow0 = block_row + ar0; if (grow0 >= M) grow0 = M - 1;
    int grow1 = block_row + ar1; if (grow1 >= M) grow1 = M - 1;
    const __half* aSrc0 = Ah + (size_t)grow0 * K + ac0;
    const __half* aSrc1 = Ah + (size_t)grow1 * K + ac1;

    const int br0 = tid / (BN / 8),         bc0 = (tid % (BN / 8)) * 8;
    const int br1 = (tid + 256) / (BN / 8), bc1 = ((tid + 256) % (BN / 8)) * 8;

    auto issue = [&](int t, int buf) {
        int k0 = t * BK;
        cp16(smem_u32(&As[(buf * BM + ar0) * AKP + ac0]), aSrc0 + k0);
        cp16(smem_u32(&As[(buf * BM + ar1) * AKP + ac1]), aSrc1 + k0);
        cp16(smem_u32(&Bs[(buf * BK + br0) * BNP + bc0]),
             Wh + (size_t)(k0 + br0) * BN + bc0);
        if (256 < BCH && tid + 256 < BCH)
            cp16(smem_u32(&Bs[(buf * BK + br1) * BNP + bc1]),
                 Wh + (size_t)(k0 + br1) * BN + bc1);
    };

    const int NT = K / BK;
#pragma unroll
    for (int s = 0; s < STAGES - 1; s++) {
        issue(s, s);
        asm volatile("cp.async.commit_group;" ::: "memory");
    }

    const int la_r = (lane & 7) + ((lane >> 3) & 1) * 8;
    const int la_c = ((lane >> 4) & 1) * 8;
    const int lb_k = (lane & 7) + ((lane >> 3) & 1) * 8;
    const int lb_n = ((lane >> 4) & 1) * 8;

    for (int t = 0; t < NT; t++) {
        asm volatile("cp.async.wait_group %0;" :: "n"(STAGES - 2) : "memory");
        __syncthreads();
        const int buf = t % STAGES;

#pragma unroll
        for (int ks = 0; ks < 2; ks++) {
            uint32_t afr[2][4];
#pragma unroll
            for (int mi = 0; mi < 2; mi++)
                ldm_x4(afr[mi], smem_u32(
                    &As[(buf * BM + wm * 32 + mi * 16 + la_r) * AKP + ks * 16 + la_c]));

            uint32_t bfr[NA][2];
#pragma unroll
            for (int ni2 = 0; ni2 < NA / 2; ni2++) {
                uint32_t tmp[4];
                ldm_x4_t(tmp, smem_u32(
                    &Bs[(buf * BK + ks * 16 + lb_k) * BNP + wn * WN + ni2 * 16 + lb_n]));
                bfr[2 * ni2][0]     = tmp[0];
                bfr[2 * ni2][1]     = tmp[1];
                bfr[2 * ni2 + 1][0] = tmp[2];
                bfr[2 * ni2 + 1][1] = tmp[3];
            }

#pragma unroll
            for (int mi = 0; mi < 2; mi++)
#pragma unroll
                for (int ni = 0; ni < NA; ni++)
                    mma_f16(acc[mi][ni], afr[mi], bfr[ni]);
        }

        int tn = t + STAGES - 1;
        if (tn < NT) issue(tn, tn % STAGES);
        asm volatile("cp.async.commit_group;" ::: "memory");
    }

#pragma unroll
    for (int mi = 0; mi < 2; mi++) {
        int rA = block_row + wm * 32 + mi * 16 + g;
        int rB = rA + 8;
        bool okA = rA < M, okB = rB < M;
#pragma unroll
        for (int ni = 0; ni < NA; ni++) {
            int col = wn * WN + ni * 8 + 2 * tq;
            if (LAYER_EPI) {
                if (okA)
                    *reinterpret_cast<__half2*>(&H16[(size_t)rA * BN + col])
                        = __floats2half2_rn(acc[mi][ni][0], acc[mi][ni][1]);
                if (okB)
                    *reinterpret_cast<__half2*>(&H16[(size_t)rB * BN + col])
                        = __floats2half2_rn(acc[mi][ni][2], acc[mi][ni][3]);
            } else {
                float bx = bias[col], by = bias[col + 1];
                if (okA)
                    *reinterpret_cast<float2*>(&OUT[(size_t)rA * BN + col])
                        = make_float2(acc[mi][ni][0] + bx, acc[mi][ni][1] + by);
                if (okB)
                    *reinterpret_cast<float2*>(&OUT[(size_t)rB * BN + col])
                        = make_float2(acc[mi][ni][2] + bx, acc[mi][ni][3] + by);
            }
        }
    }
}

// ---------------- CSR gather + self-loop + bias + relu (known-good) ----------------
__global__ __launch_bounds__(256) void k_gather(const float* __restrict__ bias) {
    int node = (blockIdx.x * 256 + threadIdx.x) >> 5;
    if (node >= N_NODES) return;
    int lane = threadIdx.x & 31;
    int beg = g_rowptr[node];
    int end = g_rowptr[node + 1];
    const bool active = lane < (HID / 4);
    const int coff = lane * 4;

    float4 acc = make_float4(0.f, 0.f, 0.f, 0.f);
#pragma unroll 4
    for (int e = beg; e < end; e++) {
        float2 ed = __ldcs(&g_edge[e]);   // streamed, evict-first
        int s = __float_as_int(ed.x);
        float w = ed.y;
        if (active) {
            uint2 p = *reinterpret_cast<const uint2*>(&g_h16[(size_t)s * HID + coff]);
            float2 f0 = __half22float2(*reinterpret_cast<__half2*>(&p.x));
            float2 f1 = __half22float2(*reinterpret_cast<__half2*>(&p.y));
            acc.x = fmaf(f0.x, w, acc.x);
            acc.y = fmaf(f0.y, w, acc.y);
            acc.z = fmaf(f1.x, w, acc.z);
            acc.w = fmaf(f1.y, w, acc.w);
        }
    }
    if (active) {
        uint2 p = *reinterpret_cast<const uint2*>(&g_h16[(size_t)node * HID + coff]);
        float2 f0 = __half22float2(*reinterpret_cast<__half2*>(&p.x));
        float2 f1 = __half22float2(*reinterpret_cast<__half2*>(&p.y));
        float d = g_dinv[node];
        float dd = d * d;
        float4 b4 = *reinterpret_cast<const float4*>(&bias[coff]);
        float r0 = fmaxf(fmaf(f0.x, dd, acc.x) + b4.x, 0.f);
        float r1 = fmaxf(fmaf(f0.y, dd, acc.y) + b4.y, 0.f);
        float r2 = fmaxf(fmaf(f1.x, dd, acc.z) + b4.z, 0.f);
        float r3 = fmaxf(fmaf(f1.y, dd, acc.w) + b4.w, 0.f);
        st_half4(&g_a16[(size_t)node * HID + coff], make_float4(r0, r1, r2, r3));
    }
}

extern "C" void kernel_launch(void* const* d_in, const int* in_sizes, int n_in,
                              void* d_out, int out_size)
{
    const float* x    = (const float*)d_in[0];
    const int*   ei   = (const int*)d_in[1];
    const float* W0   = (const float*)d_in[2];
    const float* b0   = (const float*)d_in[3];
    const float* W1   = (const float*)d_in[4];
    const float* b1   = (const float*)d_in[5];
    const float* W2   = (const float*)d_in[6];
    const float* b2   = (const float*)d_in[7];
    const float* fcW  = (const float*)d_in[8];
    const float* fcb  = (const float*)d_in[9];
    float* out = (float*)d_out;

    const int* src = ei;
    const int* dst = ei + N_EDGES;

    __half* w16; cudaGetSymbolAddress((void**)&w16, g_w16);
    __half* h16; cudaGetSymbolAddress((void**)&h16, g_h16);
    __half* a16; cudaGetSymbolAddress((void**)&a16, g_a16);
    int*    deg; cudaGetSymbolAddress((void**)&deg, g_deg);

    constexpr int SMEM_96 = 3 * (128 * 40 + 32 * (HID + 8)) * 2;   // 50688
    constexpr int SMEM_64 = 3 * (128 * 40 + 32 * (OUTD + 8)) * 2;  // 44544
    constexpr int SMEM_G0 = 4 * (128 * 40) * 4 + 4 * (32 * (HID + 8)) * 2;  // 108544

    static cudaStream_t s2 = nullptr;
    static cudaEvent_t evFork = nullptr, evJoin = nullptr;
    if (!s2) {
        cudaStreamCreateWithFlags(&s2, cudaStreamNonBlocking);
        cudaEventCreateWithFlags(&evFork, cudaEventDisableTiming);
        cudaEventCreateWithFlags(&evJoin, cudaEventDisableTiming);
        cudaFuncSetAttribute(k_gemm_tc<HID, true>,
                             cudaFuncAttributeMaxDynamicSharedMemorySize, SMEM_96);
        cudaFuncSetAttribute(k_gemm_tc<OUTD, false>,
                             cudaFuncAttributeMaxDynamicSharedMemorySize, SMEM_64);
        cudaFuncSetAttribute(k_gemm0_f32,
                             cudaFuncAttributeMaxDynamicSharedMemorySize, SMEM_G0);
    }

    const int M = N_NODES;
    dim3 gemm_grid((M + 127) / 128);
    int gather_grid = (N_NODES * 32 + 255) / 256;

    // ---- launch 1: weight conversion on s2 (tiny) ----
    cudaEventRecord(evFork, 0);
    cudaStreamWaitEvent(s2, evFork, 0);
    k_cvt_w<<<(W16_TOT / 4 + 255) / 256, 256, 0, s2>>>(W0, W1, W2, fcW);

    // ---- degree + scan1 on main ----
    cudaMemsetAsync(deg, 0, N_NODES * sizeof(int), 0);
    k_count_deg<<<(N_EDGES + 255) / 256, 256>>>(dst);
    k_scan1<<<NBLK, SCAN_BS>>>();                 // also computes dinv

    // ---- GEMM0 on s2 reads fp32 x directly (profiled slot) ----
    k_gemm0_f32<<<gemm_grid, 256, SMEM_G0, s2>>>(x, w16 + W16_W0, h16, M);
    cudaEventRecord(evJoin, s2);

    // ---- rest of CSR build on main, overlapped with GEMM0 ----
    k_scan2<<<1, 128>>>();
    k_scan3<<<(N_NODES + 255) / 256, 256>>>();
    k_fill<<<(N_EDGES + 255) / 256, 256>>>(src, dst);

    // ---- join, then layer pipeline ----
    cudaStreamWaitEvent(0, evJoin, 0);
    k_gather<<<gather_grid, 256>>>(b0);   // a16 = relu(agg0)

    k_gemm_tc<HID, true><<<gemm_grid, 256, SMEM_96>>>(
        a16, w16 + W16_W1, nullptr, h16, nullptr, M, HID);
    k_gather<<<gather_grid, 256>>>(b1);

    k_gemm_tc<HID, true><<<gemm_grid, 256, SMEM_96>>>(
        a16, w16 + W16_W2, nullptr, h16, nullptr, M, HID);
    k_gather<<<gather_grid, 256>>>(b2);

    // FC head: out = a16 @ fcW + fcb
    k_gemm_tc<OUTD, false><<<gemm_grid, 256, SMEM_64>>>(
        a16, w16 + W16_FC, fcb, nullptr, out, M, HID);
}